// round 8
// baseline (speedup 1.0000x reference)
#include <cuda_runtime.h>
#include <cuda_bf16.h>
#include <cstdint>
#include <math.h>

#define BB 8
#define SS 2048
#define TT 16384

// ---------------- float scratch ----------------
#define F_QKV  0u          // 16384*384
#define F_BUFB 6291456u    // 16384*128
#define F_BUFC 8388608u
#define F_SNF  10485760u
#define F_M    12582912u   // 8*128*128
#define F_SIM  12713984u   // 16384
#define F_QKV2 12730368u   // 16384*384
#define F_TOT  19021824u
__device__ float g_f32[F_TOT];

// ---------------- bf16 scratch (each tensor: HI then LO contiguous) ----------------
#define H_X      0u
#define H_SP     4194304u
#define H_TP     8388608u
#define H_ATT    12582912u
#define H_BUFB   16777216u
#define H_BUFH   20971520u   // 16384*512 *2
#define H_SE     37748736u
#define H_SN     41943040u
#define H_TE     46137344u
#define H_TN     50331648u
#define H_M      54525952u   // 131072*2
#define H_LWIN   54788096u   // 49152*2
#define H_LWOUT  54886400u   // 16384*2
#define H_SPATW  54919168u
#define H_TEMPW  54951936u
#define H_INTIN  54984704u   // 49152*2
#define H_INTOUT 55083008u
#define H_FW1    55115776u   // 65536*2
#define H_FW2    55246848u
#define H_ATT2   55377920u   // 2097152*2
#define BF_TOT   59572224u
__device__ __nv_bfloat16 g_bf[BF_TOT];

enum { EP_F32 = 0, EP_LN = 1, EP_GELU = 2, EP_LN2 = 3, EP_COS = 4, EP_FINAL = 5, EP_SIMDOT = 6 };

__device__ __forceinline__ uint32_t smem_to_u32(const void* p) {
    uint32_t a;
    asm("{ .reg .u64 t; cvta.to.shared.u64 t, %1; cvt.u32.u64 %0, t; }" : "=r"(a) : "l"(p));
    return a;
}

#define CP16(dst, src) do { \
    unsigned long long _gs = (unsigned long long)__cvta_generic_to_global((const void*)(src)); \
    asm volatile("cp.async.cg.shared.global [%0], [%1], 16;" :: "r"(dst), "l"(_gs)); } while (0)
#define CP_COMMIT() asm volatile("cp.async.commit_group;" ::: "memory")
#define CP_WAIT(n) asm volatile("cp.async.wait_group %0;" :: "n"(n) : "memory")

#define LDSM4(r0, r1, r2, r3, addr) \
    asm volatile("ldmatrix.sync.aligned.m8n8.x4.shared.b16 {%0,%1,%2,%3}, [%4];" \
        : "=r"(r0), "=r"(r1), "=r"(r2), "=r"(r3) : "r"(addr))
#define LDSM4T(r0, r1, r2, r3, addr) \
    asm volatile("ldmatrix.sync.aligned.m8n8.x4.trans.shared.b16 {%0,%1,%2,%3}, [%4];" \
        : "=r"(r0), "=r"(r1), "=r"(r2), "=r"(r3) : "r"(addr))
#define LDSM2T(r0, r1, addr) \
    asm volatile("ldmatrix.sync.aligned.m8n8.x2.trans.shared.b16 {%0,%1}, [%2];" \
        : "=r"(r0), "=r"(r1) : "r"(addr))

#define MMA_BF16(c, a, b) \
    asm volatile("mma.sync.aligned.m16n8k16.row.col.f32.bf16.bf16.f32 " \
        "{%0,%1,%2,%3}, {%4,%5,%6,%7}, {%8,%9}, {%0,%1,%2,%3};" \
        : "+f"((c)[0]), "+f"((c)[1]), "+f"((c)[2]), "+f"((c)[3]) \
        : "r"((a)[0]), "r"((a)[1]), "r"((a)[2]), "r"((a)[3]), "r"((b)[0]), "r"((b)[1]))

__device__ __forceinline__ void cvt_split4(float4 v, uint2& hv, uint2& lv) {
    __nv_bfloat16 h0 = __float2bfloat16_rn(v.x);
    __nv_bfloat16 h1 = __float2bfloat16_rn(v.y);
    __nv_bfloat16 h2 = __float2bfloat16_rn(v.z);
    __nv_bfloat16 h3 = __float2bfloat16_rn(v.w);
    __nv_bfloat16 l0 = __float2bfloat16_rn(v.x - __bfloat162float(h0));
    __nv_bfloat16 l1 = __float2bfloat16_rn(v.y - __bfloat162float(h1));
    __nv_bfloat16 l2 = __float2bfloat16_rn(v.z - __bfloat162float(h2));
    __nv_bfloat16 l3 = __float2bfloat16_rn(v.w - __bfloat162float(h3));
    hv.x = (uint32_t)__bfloat16_as_ushort(h0) | ((uint32_t)__bfloat16_as_ushort(h1) << 16);
    hv.y = (uint32_t)__bfloat16_as_ushort(h2) | ((uint32_t)__bfloat16_as_ushort(h3) << 16);
    lv.x = (uint32_t)__bfloat16_as_ushort(l0) | ((uint32_t)__bfloat16_as_ushort(l1) << 16);
    lv.y = (uint32_t)__bfloat16_as_ushort(l2) | ((uint32_t)__bfloat16_as_ushort(l3) << 16);
}

__device__ __forceinline__ void store_hl(__nv_bfloat16* Ch, __nv_bfloat16* Cl,
                                         size_t idx, float w0, float w1) {
    __nv_bfloat16 h0 = __float2bfloat16_rn(w0), h1 = __float2bfloat16_rn(w1);
    __nv_bfloat162 hp; hp.x = h0; hp.y = h1;
    *(__nv_bfloat162*)(Ch + idx) = hp;
    __nv_bfloat162 lp;
    lp.x = __float2bfloat16_rn(w0 - __bfloat162float(h0));
    lp.y = __float2bfloat16_rn(w1 - __bfloat162float(h1));
    *(__nv_bfloat162*)(Cl + idx) = lp;
}

__device__ __forceinline__ float gelu_f(float v) {
    return 0.5f * v * (1.0f + erff(v * 0.70710678118654752f));
}

// ============== pre-split conversion ==============
struct CvtSrc { const float* p[6]; int n[6]; unsigned off[6]; int cnt; };
__global__ void __launch_bounds__(256) cvt_k(CvtSrc s)
{
    int stride = gridDim.x * blockDim.x;
    int t = blockIdx.x * blockDim.x + threadIdx.x;
    for (int seg = 0; seg < s.cnt; seg++) {
        const float4* src = (const float4*)s.p[seg];
        __nv_bfloat16* dh = g_bf + s.off[seg];
        __nv_bfloat16* dl = dh + s.n[seg];
        int m = s.n[seg] >> 2;
        for (int i = t; i < m; i += stride) {
            uint2 hv, lv;
            cvt_split4(src[i], hv, lv);
            *(uint2*)(dh + (size_t)i * 4) = hv;
            *(uint2*)(dl + (size_t)i * 4) = lv;
        }
    }
}

__global__ void __launch_bounds__(256) cvtm_k(const float* __restrict__ src,
                                              __nv_bfloat16* dh, __nv_bfloat16* dl, int n)
{
    int t = blockIdx.x * blockDim.x + threadIdx.x;
    int m = n >> 2;
    for (int i = t; i < m; i += gridDim.x * blockDim.x) {
        uint2 hv, lv;
        cvt_split4(((const float4*)src)[i], hv, lv);
        *(uint2*)(dh + (size_t)i * 4) = hv;
        *(uint2*)(dl + (size_t)i * 4) = lv;
    }
}

__global__ void zero_k(float* p, int n)
{
    int i = blockIdx.x * 256 + threadIdx.x;
    if (i < n) p[i] = 0.f;
}

// ============== generic bf16-split GEMM: C[M,N] = A @ W^T ==============
// Tile 32(M) x 128(N), 256 threads = 8 warps (2 wm x 4 wn), warp tile 16x32.
// smem stage (25600B): AH +0 (32x80), AL +2560, BH +5120 (128x80), BL +15360.
#define GST 25600
__global__ void __launch_bounds__(256, 4) gemm_mma(
    const __nv_bfloat16* __restrict__ Ah, const __nv_bfloat16* __restrict__ Al,
    const __nv_bfloat16* __restrict__ A2h, const __nv_bfloat16* __restrict__ A2l,
    const __nv_bfloat16* __restrict__ Wh, const __nv_bfloat16* __restrict__ Wl,
    const float* __restrict__ bias, float* __restrict__ C,
    __nv_bfloat16* __restrict__ Ch, __nv_bfloat16* __restrict__ Cl,
    __nv_bfloat16* __restrict__ C2h, __nv_bfloat16* __restrict__ C2l,
    const float* __restrict__ R, const float* __restrict__ rs,
    const float* __restrict__ gam, const float* __restrict__ bet,
    int K, int ldc, int mode, int batchW)
{
    extern __shared__ char smem[];
    uint32_t sb = smem_to_u32(smem);
    const int tid = threadIdx.x, lane = tid & 31, wid = tid >> 5;
    const int wm = wid >> 2, wn = wid & 3;
    const int lr = lane >> 2, lc = lane & 3;
    const int bm = blockIdx.y * 32, bn = blockIdx.x * 128;

    const __nv_bfloat16* Auh = (A2h && bn > 0) ? A2h : Ah;
    const __nv_bfloat16* Aul = (A2h && bn > 0) ? A2l : Al;
    if (batchW) { Wh += (size_t)(bm >> 11) * (size_t)batchW; Wl += (size_t)(bm >> 11) * (size_t)batchW; }

    // A loader: threads 0..127, 32 rows x 64B, one 16B quarter per thread
    const int ra = (tid & 127) >> 2, qa = tid & 3;
    const size_t aIdx = (size_t)(bm + ra) * K + qa * 8;
    // B loader: 256 threads, 128 rows x 64B, one 32B half per thread
    const int rb = tid >> 1, hb = tid & 1;
    const size_t wIdx = (size_t)(bn + rb) * K + hb * 16;
    const __nv_bfloat16 *pAh = Auh + aIdx, *pAl = Aul + aIdx;
    const __nv_bfloat16 *pWh = Wh + wIdx, *pWl = Wl + wIdx;
    const uint32_t dA = sb + ra * 80 + qa * 16;
    const uint32_t dB = sb + 5120 + rb * 80 + hb * 32;
    const bool ldA = (tid < 128);

    float acc[4][4];
    #pragma unroll
    for (int j = 0; j < 4; j++)
        #pragma unroll
        for (int k = 0; k < 4; k++) acc[j][k] = 0.f;

    const int nch = K >> 5;

    {
        if (ldA) { CP16(dA, pAh); CP16(dA + 2560, pAl); }
        CP16(dB, pWh); CP16(dB + 16, pWh + 8);
        CP16(dB + 10240, pWl); CP16(dB + 10240 + 16, pWl + 8);
        CP_COMMIT();
    }

    for (int c = 0; c < nch; c++) {
        if (c + 1 < nch) {
            uint32_t stg = ((c + 1) & 1) * GST;
            const int co = (c + 1) * 32;
            if (ldA) { CP16(dA + stg, pAh + co); CP16(dA + stg + 2560, pAl + co); }
            CP16(dB + stg, pWh + co); CP16(dB + stg + 16, pWh + co + 8);
            CP16(dB + stg + 10240, pWl + co); CP16(dB + stg + 10240 + 16, pWl + co + 8);
            CP_COMMIT();
            CP_WAIT(1);
        } else {
            CP_WAIT(0);
        }
        __syncthreads();
        uint32_t base = sb + (c & 1) * GST;
        #pragma unroll
        for (int ks = 0; ks < 2; ks++) {
            uint32_t ah[4], al[4], bh[4][2], bl[4][2];
            {
                uint32_t addr = base + (uint32_t)((wm * 16 + (lane & 15)) * 80
                               + ks * 32 + ((lane >> 4) & 1) * 16);
                LDSM4(ah[0], ah[1], ah[2], ah[3], addr);
                LDSM4(al[0], al[1], al[2], al[3], addr + 2560);
            }
            #pragma unroll
            for (int ntp = 0; ntp < 2; ntp++) {
                int colrow = wn * 32 + ntp * 16 + ((lane >> 4) & 1) * 8 + (lane & 7);
                uint32_t addr = base + 5120 + (uint32_t)(colrow * 80
                               + ks * 32 + ((lane >> 3) & 1) * 16);
                LDSM4(bh[2 * ntp][0], bh[2 * ntp][1], bh[2 * ntp + 1][0], bh[2 * ntp + 1][1], addr);
                LDSM4(bl[2 * ntp][0], bl[2 * ntp][1], bl[2 * ntp + 1][0], bl[2 * ntp + 1][1], addr + 10240);
            }
            #pragma unroll
            for (int nt = 0; nt < 4; nt++) {
                MMA_BF16(acc[nt], ah, bh[nt]);
                MMA_BF16(acc[nt], ah, bl[nt]);
                MMA_BF16(acc[nt], al, bh[nt]);
            }
        }
        __syncthreads();
    }

    // ---------------- epilogues ----------------
    if (mode == EP_SIMDOT) {
        float* simS = (float*)smem;
        if (tid < 32) simS[tid] = 0.f;
        __syncthreads();
        {
            int row0 = bm + wm * 16 + lr;
            float d0 = 0.f, d1 = 0.f;
            #pragma unroll
            for (int nt = 0; nt < 4; nt++) {
                int col = bn + wn * 32 + nt * 8 + 2 * lc;
                float2 s0 = *(const float2*)(R + (size_t)row0 * 128 + col);
                float2 s1 = *(const float2*)(R + (size_t)(row0 + 8) * 128 + col);
                d0 += acc[nt][0] * s0.x + acc[nt][1] * s0.y;
                d1 += acc[nt][2] * s1.x + acc[nt][3] * s1.y;
            }
            d0 += __shfl_xor_sync(0xffffffffu, d0, 1);
            d0 += __shfl_xor_sync(0xffffffffu, d0, 2);
            d1 += __shfl_xor_sync(0xffffffffu, d1, 1);
            d1 += __shfl_xor_sync(0xffffffffu, d1, 2);
            if (lc == 0) {
                atomicAdd(&simS[wm * 16 + lr], d0);
                atomicAdd(&simS[wm * 16 + lr + 8], d1);
            }
        }
        __syncthreads();
        if (tid < 32) C[bm + tid] = simS[tid] * (1.f / 2048.f);
        return;
    }

    {
        int row = bm + wm * 16 + lr;
        #pragma unroll
        for (int nt = 0; nt < 4; nt++) {
            int col = bn + wn * 32 + nt * 8 + 2 * lc;
            float2 b2 = *(const float2*)(bias + col);
            float* a = acc[nt];
            a[0] += b2.x; a[1] += b2.y; a[2] += b2.x; a[3] += b2.y;
            if (mode == EP_LN || mode == EP_LN2) {
                float2 r0 = *(const float2*)(R + (size_t)row * ldc + col);
                float2 r1 = *(const float2*)(R + (size_t)(row + 8) * ldc + col);
                a[0] += r0.x; a[1] += r0.y; a[2] += r1.x; a[3] += r1.y;
            } else if (mode == EP_GELU) {
                a[0] = gelu_f(a[0]); a[1] = gelu_f(a[1]);
                a[2] = gelu_f(a[2]); a[3] = gelu_f(a[3]);
            } else if (mode == EP_FINAL) {
                float2 r0 = *(const float2*)(R + (size_t)row * ldc + col);
                float2 r1 = *(const float2*)(R + (size_t)(row + 8) * ldc + col);
                float sc0 = rs[row], sc1 = rs[row + 8];
                a[0] = r0.x + sc0 * a[0]; a[1] = r0.y + sc0 * a[1];
                a[2] = r1.x + sc1 * a[2]; a[3] = r1.y + sc1 * a[3];
            }
        }
    }

    if (mode == EP_LN || mode == EP_LN2 || mode == EP_COS) {
        float* ps = (float*)smem;        // [32][4]
        float* ps2 = ps + 128;
        {
            float p0 = 0.f, p1 = 0.f, q0 = 0.f, q1 = 0.f;
            #pragma unroll
            for (int nt = 0; nt < 4; nt++) {
                float* a = acc[nt];
                p0 += a[0] + a[1]; q0 += a[0] * a[0] + a[1] * a[1];
                p1 += a[2] + a[3]; q1 += a[2] * a[2] + a[3] * a[3];
            }
            p0 += __shfl_xor_sync(0xffffffffu, p0, 1); p0 += __shfl_xor_sync(0xffffffffu, p0, 2);
            p1 += __shfl_xor_sync(0xffffffffu, p1, 1); p1 += __shfl_xor_sync(0xffffffffu, p1, 2);
            q0 += __shfl_xor_sync(0xffffffffu, q0, 1); q0 += __shfl_xor_sync(0xffffffffu, q0, 2);
            q1 += __shfl_xor_sync(0xffffffffu, q1, 1); q1 += __shfl_xor_sync(0xffffffffu, q1, 2);
            if (lc == 0) {
                int r0l = wm * 16 + lr;
                ps[r0l * 4 + wn] = p0; ps2[r0l * 4 + wn] = q0;
                ps[(r0l + 8) * 4 + wn] = p1; ps2[(r0l + 8) * 4 + wn] = q1;
            }
        }
        __syncthreads();
        {
            int r0l = wm * 16 + lr;
            float s0 = 0.f, t0 = 0.f, s1 = 0.f, t1 = 0.f;
            #pragma unroll
            for (int w4 = 0; w4 < 4; w4++) {
                s0 += ps[r0l * 4 + w4]; t0 += ps2[r0l * 4 + w4];
                s1 += ps[(r0l + 8) * 4 + w4]; t1 += ps2[(r0l + 8) * 4 + w4];
            }
            int row0 = bm + r0l;
            if (mode == EP_COS) {
                float i0 = 1.f / fmaxf(sqrtf(t0), 1e-8f);
                float i1 = 1.f / fmaxf(sqrtf(t1), 1e-8f);
                #pragma unroll
                for (int nt = 0; nt < 4; nt++) {
                    int col = bn + wn * 32 + nt * 8 + 2 * lc;
                    float* a = acc[nt];
                    size_t i0x = (size_t)row0 * ldc + col, i1x = (size_t)(row0 + 8) * ldc + col;
                    store_hl(Ch, Cl, i0x, a[0], a[1]);
                    store_hl(Ch, Cl, i1x, a[2], a[3]);
                    float n0 = a[0] * i0, n1 = a[1] * i0, n2 = a[2] * i1, n3 = a[3] * i1;
                    store_hl(C2h, C2l, i0x, n0, n1);
                    store_hl(C2h, C2l, i1x, n2, n3);
                    if (C) {
                        *(float2*)(C + i0x) = make_float2(n0, n1);
                        *(float2*)(C + i1x) = make_float2(n2, n3);
                    }
                }
            } else {
                float mu0 = s0 * (1.f / 128.f), mu1 = s1 * (1.f / 128.f);
                float rs0 = rsqrtf(t0 * (1.f / 128.f) - mu0 * mu0 + 1e-5f);
                float rs1 = rsqrtf(t1 * (1.f / 128.f) - mu1 * mu1 + 1e-5f);
                #pragma unroll
                for (int nt = 0; nt < 4; nt++) {
                    int col = bn + wn * 32 + nt * 8 + 2 * lc;
                    float* a = acc[nt];
                    float2 g2 = *(const float2*)(gam + col);
                    float2 be2 = *(const float2*)(bet + col);
                    float w0 = (a[0] - mu0) * rs0 * g2.x + be2.x;
                    float w1 = (a[1] - mu0) * rs0 * g2.y + be2.y;
                    float w2 = (a[2] - mu1) * rs1 * g2.x + be2.x;
                    float w3 = (a[3] - mu1) * rs1 * g2.y + be2.y;
                    size_t i0x = (size_t)row0 * ldc + col, i1x = (size_t)(row0 + 8) * ldc + col;
                    *(float2*)(C + i0x) = make_float2(w0, w1);
                    *(float2*)(C + i1x) = make_float2(w2, w3);
                    if (Ch) {
                        store_hl(Ch, Cl, i0x, w0, w1);
                        store_hl(Ch, Cl, i1x, w2, w3);
                    }
                }
            }
        }
    } else {
        int row = bm + wm * 16 + lr;
        #pragma unroll
        for (int nt = 0; nt < 4; nt++) {
            int col = bn + wn * 32 + nt * 8 + 2 * lc;
            float* a = acc[nt];
            size_t i0x = (size_t)row * ldc + col, i1x = (size_t)(row + 8) * ldc + col;
            if (mode == EP_GELU) {
                store_hl(Ch, Cl, i0x, a[0], a[1]);
                store_hl(Ch, Cl, i1x, a[2], a[3]);
            } else {
                *(float2*)(C + i0x) = make_float2(a[0], a[1]);
                *(float2*)(C + i1x) = make_float2(a[2], a[3]);
            }
        }
    }
}

// ============== M covariance: M[b] += sn^T tn (contract over s) ==============
#define CST 34816
__global__ void __launch_bounds__(256) mcov_mma(
    const __nv_bfloat16* __restrict__ snh, const __nv_bfloat16* __restrict__ snl,
    const __nv_bfloat16* __restrict__ tnh, const __nv_bfloat16* __restrict__ tnl,
    float* __restrict__ M)
{
    extern __shared__ char smem[];
    uint32_t sb = smem_to_u32(smem);
    const int tid = threadIdx.x, lane = tid & 31, wid = tid >> 5;
    const int wm = wid >> 2, wn = wid & 3;
    const int lr = lane >> 2, lc = lane & 3;
    const int b = blockIdx.y, split = blockIdx.x;

    const int r = tid >> 3, q = tid & 7;
    const size_t srow0 = (size_t)b * SS + split * 128;
    const size_t gIdx = (srow0 + r) * 128 + q * 16;
    const __nv_bfloat16 *pSh = snh + gIdx, *pSl = snl + gIdx;
    const __nv_bfloat16 *pTh = tnh + gIdx, *pTl = tnl + gIdx;
    const uint32_t dBase = sb + r * 272 + q * 32;

    float acc[4][4][4];
    #pragma unroll
    for (int i = 0; i < 4; i++)
        #pragma unroll
        for (int j = 0; j < 4; j++)
            #pragma unroll
            for (int k = 0; k < 4; k++) acc[i][j][k] = 0.f;

    {
        uint32_t d = dBase;
        CP16(d, pSh); CP16(d + 16, pSh + 8);
        CP16(d + 8704, pSl); CP16(d + 8704 + 16, pSl + 8);
        CP16(d + 17408, pTh); CP16(d + 17408 + 16, pTh + 8);
        CP16(d + 26112, pTl); CP16(d + 26112 + 16, pTl + 8);
        CP_COMMIT();
    }

    for (int c = 0; c < 4; c++) {
        if (c + 1 < 4) {
            uint32_t d = dBase + ((c + 1) & 1) * CST;
            const size_t co = (size_t)(c + 1) * 32 * 128;
            CP16(d, pSh + co); CP16(d + 16, pSh + co + 8);
            CP16(d + 8704, pSl + co); CP16(d + 8704 + 16, pSl + co + 8);
            CP16(d + 17408, pTh + co); CP16(d + 17408 + 16, pTh + co + 8);
            CP16(d + 26112, pTl + co); CP16(d + 26112 + 16, pTl + co + 8);
            CP_COMMIT();
            CP_WAIT(1);
        } else {
            CP_WAIT(0);
        }
        __syncthreads();
        uint32_t base = sb + (c & 1) * CST;
        #pragma unroll
        for (int ks = 0; ks < 2; ks++) {
            uint32_t ah[4][4], al[4][4], bh[4][2], bl[4][2];
            #pragma unroll
            for (int mt = 0; mt < 4; mt++) {
                int rowk = ks * 16 + (lane & 7) + ((lane >> 4) & 1) * 8;
                int colm = wm * 64 + mt * 16 + ((lane >> 3) & 1) * 8;
                uint32_t addr = base + (uint32_t)(rowk * 272 + colm * 2);
                LDSM4T(ah[mt][0], ah[mt][1], ah[mt][2], ah[mt][3], addr);
                LDSM4T(al[mt][0], al[mt][1], al[mt][2], al[mt][3], addr + 8704);
            }
            #pragma unroll
            for (int nt = 0; nt < 4; nt++) {
                int rowk = ks * 16 + (lane & 15);
                int coln = wn * 32 + nt * 8;
                uint32_t addr = base + 17408 + (uint32_t)(rowk * 272 + coln * 2);
                LDSM2T(bh[nt][0], bh[nt][1], addr);
                LDSM2T(bl[nt][0], bl[nt][1], addr + 8704);
            }
            #pragma unroll
            for (int mt = 0; mt < 4; mt++)
                #pragma unroll
                for (int nt = 0; nt < 4; nt++) {
                    MMA_BF16(acc[mt][nt], ah[mt], bh[nt]);
                    MMA_BF16(acc[mt][nt], ah[mt], bl[nt]);
                    MMA_BF16(acc[mt][nt], al[mt], bh[nt]);
                }
        }
        __syncthreads();
    }

    float* Mb = M + (size_t)b * 16384;
    #pragma unroll
    for (int mt = 0; mt < 4; mt++) {
        int row = wm * 64 + mt * 16 + lr;
        #pragma unroll
        for (int nt = 0; nt < 4; nt++) {
            int col = wn * 32 + nt * 8 + 2 * lc;
            atomicAdd(&Mb[(size_t)row * 128 + col], acc[mt][nt][0]);
            atomicAdd(&Mb[(size_t)row * 128 + col + 1], acc[mt][nt][1]);
            atomicAdd(&Mb[(size_t)(row + 8) * 128 + col], acc[mt][nt][2]);
            atomicAdd(&Mb[(size_t)(row + 8) * 128 + col + 1], acc[mt][nt][3]);
        }
    }
}

// ---------------- local windowed causal attention ----------------
__global__ __launch_bounds__(64) void lw_attn_k(const float* __restrict__ qkv,
                                                __nv_bfloat16* __restrict__ Ch,
                                                __nv_bfloat16* __restrict__ Cl)
{
    int g = blockIdx.x, h = blockIdx.y, i = threadIdx.x;
    __shared__ float ks[64][17];
    __shared__ float vs[64][17];
    size_t tbase = (size_t)g * 64;
    const float* kp = qkv + (tbase + i) * 384 + 128 + h * 16;
    const float* vp = kp + 128;
    #pragma unroll
    for (int d = 0; d < 16; d++) { ks[i][d] = kp[d]; vs[i][d] = vp[d]; }
    float q[16];
    const float* qp = qkv + (tbase + i) * 384 + h * 16;
    #pragma unroll
    for (int d = 0; d < 16; d++) q[d] = qp[d];
    __syncthreads();
    float sc[64];
    float mx = -1e30f;
    #pragma unroll
    for (int j = 0; j < 64; j++) {
        float dv = 0.f;
        #pragma unroll
        for (int d = 0; d < 16; d++) dv += q[d] * ks[j][d];
        sc[j] = (j <= i) ? dv * 0.25f : -INFINITY;
        mx = fmaxf(mx, sc[j]);
    }
    float sum = 0.f;
    #pragma unroll
    for (int j = 0; j < 64; j++) { float e = expf(sc[j] - mx); sc[j] = e; sum += e; }
    float o[16] = {};
    #pragma unroll
    for (int j = 0; j < 64; j++) {
        float w = sc[j];
        #pragma unroll
        for (int d = 0; d < 16; d++) o[d] += w * vs[j][d];
    }
    float inv = 1.f / sum;
    size_t ob = (tbase + i) * 128 + h * 16;
    #pragma unroll
    for (int d = 0; d < 16; d += 2)
        store_hl(Ch, Cl, ob + d, o[d] * inv, o[d + 1] * inv);
}

// ---------------- interaction MHA (len = B = 8) ----------------
__global__ __launch_bounds__(64) void int_attn_k(const float* __restrict__ qkv,
                                                 __nv_bfloat16* __restrict__ Ch,
                                                 __nv_bfloat16* __restrict__ Cl)
{
    int s = blockIdx.x, tid = threadIdx.x;
    __shared__ float kvs[8][256];
    for (int idx = tid; idx < 8 * 256; idx += 64) {
        int jb = idx >> 8, c = idx & 255;
        kvs[jb][c] = qkv[((size_t)jb * SS + s) * 384 + 128 + c];
    }
    __syncthreads();
    int h = tid >> 3, qb = tid & 7;
    float q[16];
    const float* qp = qkv + ((size_t)qb * SS + s) * 384 + h * 16;
    #pragma unroll
    for (int d = 0; d < 16; d++) q[d] = qp[d];
    float sc[8];
    float mx = -1e30f;
    #pragma unroll
    for (int jb = 0; jb < 8; jb++) {
        float dv = 0.f;
        #pragma unroll
        for (int d = 0; d < 16; d++) dv += q[d] * kvs[jb][h * 16 + d];
        sc[jb] = dv * 0.25f;
        mx = fmaxf(mx, sc[jb]);
    }
    float sum = 0.f;
    #pragma unroll
    for (int jb = 0; jb < 8; jb++) { float e = expf(sc[jb] - mx); sc[jb] = e; sum += e; }
    float o[16] = {};
    #pragma unroll
    for (int jb = 0; jb < 8; jb++) {
        float w = sc[jb];
        #pragma unroll
        for (int d = 0; d < 16; d++) o[d] += w * kvs[jb][128 + h * 16 + d];
    }
    float inv = 1.f / sum;
    size_t ob = ((size_t)qb * SS + s) * 128 + h * 16;
    #pragma unroll
    for (int d = 0; d < 16; d += 2)
        store_hl(Ch, Cl, ob + d, o[d] * inv, o[d + 1] * inv);
}

extern "C" void kernel_launch(void* const* d_in, const int* in_sizes, int n_in,
                              void* d_out, int out_size)
{
    const float* x        = (const float*)d_in[0];
    const float* sp       = (const float*)d_in[1];
    const float* tp       = (const float*)d_in[2];
    const float* lw_in_b  = (const float*)d_in[4];
    const float* lw_out_b = (const float*)d_in[6];
    const float* spat_b   = (const float*)d_in[8];
    const float* temp_b   = (const float*)d_in[10];
    const float* int_in_b = (const float*)d_in[12];
    const float* int_out_b= (const float*)d_in[14];
    const float* ffn_b1   = (const float*)d_in[16];
    const float* ffn_b2   = (const float*)d_in[18];
    const float* ln1_g    = (const float*)d_in[19];
    const float* ln1_b    = (const float*)d_in[20];
    const float* ln2_g    = (const float*)d_in[21];
    const float* ln2_b    = (const float*)d_in[22];
    float* out = (float*)d_out;

    float* f32 = nullptr;
    __nv_bfloat16* bf = nullptr;
    cudaGetSymbolAddress((void**)&f32, g_f32);
    cudaGetSymbolAddress((void**)&bf, g_bf);

    static cudaStream_t s2 = nullptr;
    static cudaEvent_t evF = nullptr, evJ = nullptr;
    static bool init_done = false;
    if (!init_done) {
        cudaFuncSetAttribute(gemm_mma, cudaFuncAttributeMaxDynamicSharedMemorySize, 2 * GST);
        cudaFuncSetAttribute(mcov_mma, cudaFuncAttributeMaxDynamicSharedMemorySize, 2 * CST);
        cudaStreamCreateWithFlags(&s2, cudaStreamNonBlocking);
        cudaEventCreateWithFlags(&evF, cudaEventDisableTiming);
        cudaEventCreateWithFlags(&evJ, cudaEventDisableTiming);
        init_done = true;
    }

    float* qkv   = f32 + F_QKV;
    float* qkv2  = f32 + F_QKV2;
    float* bufb  = f32 + F_BUFB;
    float* bufc  = f32 + F_BUFC;
    float* snf   = f32 + F_SNF;
    float* bM    = f32 + F_M;
    float* bsim  = f32 + F_SIM;

    #define BH(o) (bf + (o))
    #define BL(o, n) (bf + (o) + (n))
    const unsigned NT = 2097152;

    // ---- fork point ----
    cudaEventRecord(evF, 0);
    cudaStreamWaitEvent(s2, evF, 0);

    // ===== main stream: x-chain =====
    {
        CvtSrc cs;
        cs.cnt = 5;
        cs.p[0] = x;                         cs.n[0] = 2097152; cs.off[0] = H_X;
        cs.p[1] = (const float*)d_in[3];     cs.n[1] = 49152;   cs.off[1] = H_LWIN;
        cs.p[2] = (const float*)d_in[5];     cs.n[2] = 16384;   cs.off[2] = H_LWOUT;
        cs.p[3] = (const float*)d_in[15];    cs.n[3] = 65536;   cs.off[3] = H_FW1;
        cs.p[4] = (const float*)d_in[17];    cs.n[4] = 65536;   cs.off[4] = H_FW2;
        cvt_k<<<296, 256>>>(cs);
    }
    gemm_mma<<<dim3(3, 512), 256, 2 * GST>>>(
        BH(H_X), BL(H_X, NT), nullptr, nullptr, BH(H_LWIN), BL(H_LWIN, 49152),
        lw_in_b, qkv, nullptr, nullptr, nullptr, nullptr, nullptr, nullptr,
        nullptr, nullptr, 128, 384, EP_F32, 0);
    lw_attn_k<<<dim3(256, 8), 64>>>(qkv, BH(H_ATT), BL(H_ATT, NT));
    gemm_mma<<<dim3(1, 512), 256, 2 * GST>>>(
        BH(H_ATT), BL(H_ATT, NT), nullptr, nullptr, BH(H_LWOUT), BL(H_LWOUT, 16384),
        lw_out_b, bufb, BH(H_BUFB), BL(H_BUFB, NT), nullptr, nullptr,
        x, nullptr, ln1_g, ln1_b, 128, 128, EP_LN, 0);
    gemm_mma<<<dim3(4, 512), 256, 2 * GST>>>(
        BH(H_BUFB), BL(H_BUFB, NT), nullptr, nullptr, BH(H_FW1), BL(H_FW1, 65536),
        ffn_b1, nullptr, BH(H_BUFH), BL(H_BUFH, 8388608), nullptr, nullptr,
        nullptr, nullptr, nullptr, nullptr, 128, 512, EP_GELU, 0);
    gemm_mma<<<dim3(1, 512), 256, 2 * GST>>>(
        BH(H_BUFH), BL(H_BUFH, 8388608), nullptr, nullptr, BH(H_FW2), BL(H_FW2, 65536),
        ffn_b2, bufc, nullptr, nullptr, nullptr, nullptr,
        bufb, nullptr, ln2_g, ln2_b, 512, 128, EP_LN2, 0);

    // ===== stream 2: spatio-temporal chain =====
    {
        CvtSrc cs;
        cs.cnt = 6;
        cs.p[0] = sp;                        cs.n[0] = 2097152; cs.off[0] = H_SP;
        cs.p[1] = tp;                        cs.n[1] = 2097152; cs.off[1] = H_TP;
        cs.p[2] = (const float*)d_in[7];     cs.n[2] = 16384;   cs.off[2] = H_SPATW;
        cs.p[3] = (const float*)d_in[9];     cs.n[3] = 16384;   cs.off[3] = H_TEMPW;
        cs.p[4] = (const float*)d_in[11];    cs.n[4] = 49152;   cs.off[4] = H_INTIN;
        cs.p[5] = (const float*)d_in[13];    cs.n[5] = 16384;   cs.off[5] = H_INTOUT;
        cvt_k<<<296, 256, 0, s2>>>(cs);
    }
    zero_k<<<512, 256, 0, s2>>>(bM, 8 * 128 * 128);
    gemm_mma<<<dim3(1, 512), 256, 2 * GST, s2>>>(
        BH(H_SP), BL(H_SP, NT), nullptr, nullptr, BH(H_SPATW), BL(H_SPATW, 16384),
        spat_b, snf, BH(H_SE), BL(H_SE, NT), BH(H_SN), BL(H_SN, NT),
        nullptr, nullptr, nullptr, nullptr, 128, 128, EP_COS, 0);
    gemm_mma<<<dim3(1, 512), 256, 2 * GST, s2>>>(
        BH(H_TP), BL(H_TP, NT), nullptr, nullptr, BH(H_TEMPW), BL(H_TEMPW, 16384),
        temp_b, nullptr, BH(H_TE), BL(H_TE, NT), BH(H_TN), BL(H_TN, NT),
        nullptr, nullptr, nullptr, nullptr, 128, 128, EP_COS, 0);
    mcov_mma<<<dim3(16, 8), 256, 2 * CST, s2>>>(
        BH(H_SN), BL(H_SN, NT), BH(H_TN), BL(H_TN, NT), bM);
    cvtm_k<<<128, 256, 0, s2>>>(bM, BH(H_M), BL(H_M, 131072), 131072);
    gemm_mma<<<dim3(1, 512), 256, 2 * GST, s2>>>(
        BH(H_TN), BL(H_TN, NT), nullptr, nullptr, BH(H_M), BL(H_M, 131072),
        nullptr, bsim, nullptr, nullptr, nullptr, nullptr,
        snf, nullptr, nullptr, nullptr, 128, 0, EP_SIMDOT, 16384);
    gemm_mma<<<dim3(3, 512), 256, 2 * GST, s2>>>(
        BH(H_SE), BL(H_SE, NT), BH(H_TE), BL(H_TE, NT), BH(H_INTIN), BL(H_INTIN, 49152),
        int_in_b, qkv2, nullptr, nullptr, nullptr, nullptr, nullptr, nullptr,
        nullptr, nullptr, 128, 384, EP_F32, 0);
    int_attn_k<<<SS, 64, 0, s2>>>(qkv2, BH(H_ATT2), BL(H_ATT2, NT));
    cudaEventRecord(evJ, s2);

    // ---- join + final ----
    cudaStreamWaitEvent(0, evJ, 0);
    gemm_mma<<<dim3(1, 512), 256, 2 * GST>>>(
        BH(H_ATT2), BL(H_ATT2, NT), nullptr, nullptr, BH(H_INTOUT), BL(H_INTOUT, 16384),
        int_out_b, out, nullptr, nullptr, nullptr, nullptr,
        bufc, bsim, nullptr, nullptr, 128, 128, EP_FINAL, 0);
}

// round 9
// speedup vs baseline: 1.1712x; 1.1712x over previous
#include <cuda_runtime.h>
#include <cuda_bf16.h>
#include <cstdint>
#include <math.h>

#define BB 8
#define SS 2048
#define TT 16384

// ---------------- float scratch ----------------
#define F_QKV  0u          // 16384*384
#define F_BUFB 6291456u    // 16384*128
#define F_BUFC 8388608u
#define F_SNF  10485760u
#define F_M    12582912u   // 8*128*128
#define F_SIM  12713984u   // 16384
#define F_QKV2 12730368u   // 16384*384
#define F_TOT  19021824u
__device__ float g_f32[F_TOT];

// ---------------- bf16 scratch (each tensor: HI then LO contiguous) ----------------
#define H_X      0u
#define H_SP     4194304u
#define H_TP     8388608u
#define H_ATT    12582912u
#define H_BUFB   16777216u
#define H_BUFH   20971520u   // 16384*512 *2
#define H_SE     37748736u
#define H_SN     41943040u
#define H_TE     46137344u
#define H_TN     50331648u
#define H_M      54525952u   // 131072*2
#define H_LWIN   54788096u   // 49152*2
#define H_LWOUT  54886400u   // 16384*2
#define H_SPATW  54919168u
#define H_TEMPW  54951936u
#define H_INTIN  54984704u   // 49152*2
#define H_INTOUT 55083008u
#define H_FW1    55115776u   // 65536*2
#define H_FW2    55246848u
#define H_ATT2   55377920u   // 2097152*2
#define BF_TOT   59572224u
__device__ __nv_bfloat16 g_bf[BF_TOT];

enum { EP_F32 = 0, EP_LN = 1, EP_GELU = 2, EP_LN2 = 3, EP_COS = 4, EP_FINAL = 5, EP_SIMDOT = 6 };

__device__ __forceinline__ uint32_t smem_to_u32(const void* p) {
    uint32_t a;
    asm("{ .reg .u64 t; cvta.to.shared.u64 t, %1; cvt.u32.u64 %0, t; }" : "=r"(a) : "l"(p));
    return a;
}

#define CP16(dst, src) do { \
    unsigned long long _gs = (unsigned long long)__cvta_generic_to_global((const void*)(src)); \
    asm volatile("cp.async.cg.shared.global [%0], [%1], 16;" :: "r"(dst), "l"(_gs)); } while (0)
#define CP_COMMIT() asm volatile("cp.async.commit_group;" ::: "memory")
#define CP_WAIT(n) asm volatile("cp.async.wait_group %0;" :: "n"(n) : "memory")

#define LDSM4(r0, r1, r2, r3, addr) \
    asm volatile("ldmatrix.sync.aligned.m8n8.x4.shared.b16 {%0,%1,%2,%3}, [%4];" \
        : "=r"(r0), "=r"(r1), "=r"(r2), "=r"(r3) : "r"(addr))
#define LDSM4T(r0, r1, r2, r3, addr) \
    asm volatile("ldmatrix.sync.aligned.m8n8.x4.trans.shared.b16 {%0,%1,%2,%3}, [%4];" \
        : "=r"(r0), "=r"(r1), "=r"(r2), "=r"(r3) : "r"(addr))
#define LDSM2T(r0, r1, addr) \
    asm volatile("ldmatrix.sync.aligned.m8n8.x2.trans.shared.b16 {%0,%1}, [%2];" \
        : "=r"(r0), "=r"(r1) : "r"(addr))

#define MMA_BF16(c, a, b) \
    asm volatile("mma.sync.aligned.m16n8k16.row.col.f32.bf16.bf16.f32 " \
        "{%0,%1,%2,%3}, {%4,%5,%6,%7}, {%8,%9}, {%0,%1,%2,%3};" \
        : "+f"((c)[0]), "+f"((c)[1]), "+f"((c)[2]), "+f"((c)[3]) \
        : "r"((a)[0]), "r"((a)[1]), "r"((a)[2]), "r"((a)[3]), "r"((b)[0]), "r"((b)[1]))

__device__ __forceinline__ void cvt_split4(float4 v, uint2& hv, uint2& lv) {
    __nv_bfloat16 h0 = __float2bfloat16_rn(v.x);
    __nv_bfloat16 h1 = __float2bfloat16_rn(v.y);
    __nv_bfloat16 h2 = __float2bfloat16_rn(v.z);
    __nv_bfloat16 h3 = __float2bfloat16_rn(v.w);
    __nv_bfloat16 l0 = __float2bfloat16_rn(v.x - __bfloat162float(h0));
    __nv_bfloat16 l1 = __float2bfloat16_rn(v.y - __bfloat162float(h1));
    __nv_bfloat16 l2 = __float2bfloat16_rn(v.z - __bfloat162float(h2));
    __nv_bfloat16 l3 = __float2bfloat16_rn(v.w - __bfloat162float(h3));
    hv.x = (uint32_t)__bfloat16_as_ushort(h0) | ((uint32_t)__bfloat16_as_ushort(h1) << 16);
    hv.y = (uint32_t)__bfloat16_as_ushort(h2) | ((uint32_t)__bfloat16_as_ushort(h3) << 16);
    lv.x = (uint32_t)__bfloat16_as_ushort(l0) | ((uint32_t)__bfloat16_as_ushort(l1) << 16);
    lv.y = (uint32_t)__bfloat16_as_ushort(l2) | ((uint32_t)__bfloat16_as_ushort(l3) << 16);
}

__device__ __forceinline__ void store_hl(__nv_bfloat16* Ch, __nv_bfloat16* Cl,
                                         size_t idx, float w0, float w1) {
    __nv_bfloat16 h0 = __float2bfloat16_rn(w0), h1 = __float2bfloat16_rn(w1);
    __nv_bfloat162 hp; hp.x = h0; hp.y = h1;
    *(__nv_bfloat162*)(Ch + idx) = hp;
    __nv_bfloat162 lp;
    lp.x = __float2bfloat16_rn(w0 - __bfloat162float(h0));
    lp.y = __float2bfloat16_rn(w1 - __bfloat162float(h1));
    *(__nv_bfloat162*)(Cl + idx) = lp;
}

__device__ __forceinline__ float gelu_f(float v) {
    return 0.5f * v * (1.0f + erff(v * 0.70710678118654752f));
}

// ============== pre-split conversion ==============
struct CvtSrc { const float* p[6]; int n[6]; unsigned off[6]; int cnt; };
__global__ void __launch_bounds__(256) cvt_k(CvtSrc s)
{
    int stride = gridDim.x * blockDim.x;
    int t = blockIdx.x * blockDim.x + threadIdx.x;
    for (int seg = 0; seg < s.cnt; seg++) {
        const float4* src = (const float4*)s.p[seg];
        __nv_bfloat16* dh = g_bf + s.off[seg];
        __nv_bfloat16* dl = dh + s.n[seg];
        int m = s.n[seg] >> 2;
        for (int i = t; i < m; i += stride) {
            uint2 hv, lv;
            cvt_split4(src[i], hv, lv);
            *(uint2*)(dh + (size_t)i * 4) = hv;
            *(uint2*)(dl + (size_t)i * 4) = lv;
        }
    }
}

__global__ void __launch_bounds__(256) cvtm_k(const float* __restrict__ src,
                                              __nv_bfloat16* dh, __nv_bfloat16* dl, int n)
{
    int t = blockIdx.x * blockDim.x + threadIdx.x;
    int m = n >> 2;
    for (int i = t; i < m; i += gridDim.x * blockDim.x) {
        uint2 hv, lv;
        cvt_split4(((const float4*)src)[i], hv, lv);
        *(uint2*)(dh + (size_t)i * 4) = hv;
        *(uint2*)(dl + (size_t)i * 4) = lv;
    }
}

__global__ void zero_k(float* p, int n)
{
    int i = blockIdx.x * 256 + threadIdx.x;
    if (i < n) p[i] = 0.f;
}

// ============== generic bf16-split GEMM: C[M,N] = A @ W^T ==============
// Tile 64(M) x 128(N), 256 threads = 8 warps (2 wm x 4 wn), warp tile 32x32.
// smem stage (30720B): AH +0 (64x80), AL +5120, BH +10240 (128x80), BL +20480.
#define GST 30720
__global__ void __launch_bounds__(256, 3) gemm_mma(
    const __nv_bfloat16* __restrict__ Ah, const __nv_bfloat16* __restrict__ Al,
    const __nv_bfloat16* __restrict__ A2h, const __nv_bfloat16* __restrict__ A2l,
    const __nv_bfloat16* __restrict__ Wh, const __nv_bfloat16* __restrict__ Wl,
    const float* __restrict__ bias, float* __restrict__ C,
    __nv_bfloat16* __restrict__ Ch, __nv_bfloat16* __restrict__ Cl,
    __nv_bfloat16* __restrict__ C2h, __nv_bfloat16* __restrict__ C2l,
    const float* __restrict__ R, const float* __restrict__ rs,
    const float* __restrict__ gam, const float* __restrict__ bet,
    int K, int ldc, int mode, int batchW)
{
    extern __shared__ char smem[];
    uint32_t sb = smem_to_u32(smem);
    const int tid = threadIdx.x, lane = tid & 31, wid = tid >> 5;
    const int wm = wid >> 2, wn = wid & 3;
    const int lr = lane >> 2, lc = lane & 3;
    const int bm = blockIdx.y * 64, bn = blockIdx.x * 128;

    const __nv_bfloat16* Auh = (A2h && bn > 0) ? A2h : Ah;
    const __nv_bfloat16* Aul = (A2h && bn > 0) ? A2l : Al;
    if (batchW) { Wh += (size_t)(bm >> 11) * (size_t)batchW; Wl += (size_t)(bm >> 11) * (size_t)batchW; }

    // A loader: 64 rows x 64B, one 16B quarter per thread
    const int ra = tid >> 2, qa = tid & 3;
    const size_t aIdx = (size_t)(bm + ra) * K + qa * 8;
    // B loader: 128 rows x 64B, one 32B half per thread
    const int rb = tid >> 1, hb = tid & 1;
    const size_t wIdx = (size_t)(bn + rb) * K + hb * 16;
    const __nv_bfloat16 *pAh = Auh + aIdx, *pAl = Aul + aIdx;
    const __nv_bfloat16 *pWh = Wh + wIdx, *pWl = Wl + wIdx;
    const uint32_t dA = sb + ra * 80 + qa * 16;
    const uint32_t dB = sb + 10240 + rb * 80 + hb * 32;

    float acc[2][4][4];
    #pragma unroll
    for (int i = 0; i < 2; i++)
        #pragma unroll
        for (int j = 0; j < 4; j++)
            #pragma unroll
            for (int k = 0; k < 4; k++) acc[i][j][k] = 0.f;

    const int nch = K >> 5;

    {
        CP16(dA, pAh); CP16(dA + 5120, pAl);
        CP16(dB, pWh); CP16(dB + 16, pWh + 8);
        CP16(dB + 10240, pWl); CP16(dB + 10240 + 16, pWl + 8);
        CP_COMMIT();
    }

    for (int c = 0; c < nch; c++) {
        if (c + 1 < nch) {
            uint32_t stg = ((c + 1) & 1) * GST;
            const int co = (c + 1) * 32;
            CP16(dA + stg, pAh + co); CP16(dA + stg + 5120, pAl + co);
            CP16(dB + stg, pWh + co); CP16(dB + stg + 16, pWh + co + 8);
            CP16(dB + stg + 10240, pWl + co); CP16(dB + stg + 10240 + 16, pWl + co + 8);
            CP_COMMIT();
            CP_WAIT(1);
        } else {
            CP_WAIT(0);
        }
        __syncthreads();
        uint32_t base = sb + (c & 1) * GST;
        #pragma unroll
        for (int ks = 0; ks < 2; ks++) {
            uint32_t ah[2][4], al[2][4], bh[4][2], bl[4][2];
            #pragma unroll
            for (int mt = 0; mt < 2; mt++) {
                uint32_t addr = base + (uint32_t)((wm * 32 + mt * 16 + (lane & 15)) * 80
                               + ks * 32 + ((lane >> 4) & 1) * 16);
                LDSM4(ah[mt][0], ah[mt][1], ah[mt][2], ah[mt][3], addr);
                LDSM4(al[mt][0], al[mt][1], al[mt][2], al[mt][3], addr + 5120);
            }
            #pragma unroll
            for (int ntp = 0; ntp < 2; ntp++) {
                int colrow = wn * 32 + ntp * 16 + ((lane >> 4) & 1) * 8 + (lane & 7);
                uint32_t addr = base + 10240 + (uint32_t)(colrow * 80
                               + ks * 32 + ((lane >> 3) & 1) * 16);
                LDSM4(bh[2 * ntp][0], bh[2 * ntp][1], bh[2 * ntp + 1][0], bh[2 * ntp + 1][1], addr);
                LDSM4(bl[2 * ntp][0], bl[2 * ntp][1], bl[2 * ntp + 1][0], bl[2 * ntp + 1][1], addr + 10240);
            }
            // 3 passes: consecutive MMAs hit DIFFERENT accumulators (no RAW stall)
            #pragma unroll
            for (int mt = 0; mt < 2; mt++)
                #pragma unroll
                for (int nt = 0; nt < 4; nt++)
                    MMA_BF16(acc[mt][nt], ah[mt], bh[nt]);
            #pragma unroll
            for (int mt = 0; mt < 2; mt++)
                #pragma unroll
                for (int nt = 0; nt < 4; nt++)
                    MMA_BF16(acc[mt][nt], ah[mt], bl[nt]);
            #pragma unroll
            for (int mt = 0; mt < 2; mt++)
                #pragma unroll
                for (int nt = 0; nt < 4; nt++)
                    MMA_BF16(acc[mt][nt], al[mt], bh[nt]);
        }
        __syncthreads();
    }

    // ---------------- epilogues ----------------
    if (mode == EP_SIMDOT) {
        float* simS = (float*)smem;
        if (tid < 64) simS[tid] = 0.f;
        __syncthreads();
        #pragma unroll
        for (int mt = 0; mt < 2; mt++) {
            int row0 = bm + wm * 32 + mt * 16 + lr;
            float d0 = 0.f, d1 = 0.f;
            #pragma unroll
            for (int nt = 0; nt < 4; nt++) {
                int col = bn + wn * 32 + nt * 8 + 2 * lc;
                float2 s0 = *(const float2*)(R + (size_t)row0 * 128 + col);
                float2 s1 = *(const float2*)(R + (size_t)(row0 + 8) * 128 + col);
                d0 += acc[mt][nt][0] * s0.x + acc[mt][nt][1] * s0.y;
                d1 += acc[mt][nt][2] * s1.x + acc[mt][nt][3] * s1.y;
            }
            d0 += __shfl_xor_sync(0xffffffffu, d0, 1);
            d0 += __shfl_xor_sync(0xffffffffu, d0, 2);
            d1 += __shfl_xor_sync(0xffffffffu, d1, 1);
            d1 += __shfl_xor_sync(0xffffffffu, d1, 2);
            if (lc == 0) {
                atomicAdd(&simS[wm * 32 + mt * 16 + lr], d0);
                atomicAdd(&simS[wm * 32 + mt * 16 + lr + 8], d1);
            }
        }
        __syncthreads();
        if (tid < 64) C[bm + tid] = simS[tid] * (1.f / 2048.f);
        return;
    }

    #pragma unroll
    for (int mt = 0; mt < 2; mt++) {
        int row = bm + wm * 32 + mt * 16 + lr;
        #pragma unroll
        for (int nt = 0; nt < 4; nt++) {
            int col = bn + wn * 32 + nt * 8 + 2 * lc;
            float2 b2 = *(const float2*)(bias + col);
            float* a = acc[mt][nt];
            a[0] += b2.x; a[1] += b2.y; a[2] += b2.x; a[3] += b2.y;
            if (mode == EP_LN || mode == EP_LN2) {
                float2 r0 = *(const float2*)(R + (size_t)row * ldc + col);
                float2 r1 = *(const float2*)(R + (size_t)(row + 8) * ldc + col);
                a[0] += r0.x; a[1] += r0.y; a[2] += r1.x; a[3] += r1.y;
            } else if (mode == EP_GELU) {
                a[0] = gelu_f(a[0]); a[1] = gelu_f(a[1]);
                a[2] = gelu_f(a[2]); a[3] = gelu_f(a[3]);
            } else if (mode == EP_FINAL) {
                float2 r0 = *(const float2*)(R + (size_t)row * ldc + col);
                float2 r1 = *(const float2*)(R + (size_t)(row + 8) * ldc + col);
                float sc0 = rs[row], sc1 = rs[row + 8];
                a[0] = r0.x + sc0 * a[0]; a[1] = r0.y + sc0 * a[1];
                a[2] = r1.x + sc1 * a[2]; a[3] = r1.y + sc1 * a[3];
            }
        }
    }

    if (mode == EP_LN || mode == EP_LN2 || mode == EP_COS) {
        float* ps = (float*)smem;        // [64][4]
        float* ps2 = ps + 256;
        #pragma unroll
        for (int mt = 0; mt < 2; mt++) {
            float p0 = 0.f, p1 = 0.f, q0 = 0.f, q1 = 0.f;
            #pragma unroll
            for (int nt = 0; nt < 4; nt++) {
                float* a = acc[mt][nt];
                p0 += a[0] + a[1]; q0 += a[0] * a[0] + a[1] * a[1];
                p1 += a[2] + a[3]; q1 += a[2] * a[2] + a[3] * a[3];
            }
            p0 += __shfl_xor_sync(0xffffffffu, p0, 1); p0 += __shfl_xor_sync(0xffffffffu, p0, 2);
            p1 += __shfl_xor_sync(0xffffffffu, p1, 1); p1 += __shfl_xor_sync(0xffffffffu, p1, 2);
            q0 += __shfl_xor_sync(0xffffffffu, q0, 1); q0 += __shfl_xor_sync(0xffffffffu, q0, 2);
            q1 += __shfl_xor_sync(0xffffffffu, q1, 1); q1 += __shfl_xor_sync(0xffffffffu, q1, 2);
            if (lc == 0) {
                int r0l = wm * 32 + mt * 16 + lr;
                ps[r0l * 4 + wn] = p0; ps2[r0l * 4 + wn] = q0;
                ps[(r0l + 8) * 4 + wn] = p1; ps2[(r0l + 8) * 4 + wn] = q1;
            }
        }
        __syncthreads();
        #pragma unroll
        for (int mt = 0; mt < 2; mt++) {
            int r0l = wm * 32 + mt * 16 + lr;
            float s0 = 0.f, t0 = 0.f, s1 = 0.f, t1 = 0.f;
            #pragma unroll
            for (int w4 = 0; w4 < 4; w4++) {
                s0 += ps[r0l * 4 + w4]; t0 += ps2[r0l * 4 + w4];
                s1 += ps[(r0l + 8) * 4 + w4]; t1 += ps2[(r0l + 8) * 4 + w4];
            }
            int row0 = bm + r0l;
            if (mode == EP_COS) {
                float i0 = 1.f / fmaxf(sqrtf(t0), 1e-8f);
                float i1 = 1.f / fmaxf(sqrtf(t1), 1e-8f);
                #pragma unroll
                for (int nt = 0; nt < 4; nt++) {
                    int col = bn + wn * 32 + nt * 8 + 2 * lc;
                    float* a = acc[mt][nt];
                    size_t i0x = (size_t)row0 * ldc + col, i1x = (size_t)(row0 + 8) * ldc + col;
                    store_hl(Ch, Cl, i0x, a[0], a[1]);
                    store_hl(Ch, Cl, i1x, a[2], a[3]);
                    float n0 = a[0] * i0, n1 = a[1] * i0, n2 = a[2] * i1, n3 = a[3] * i1;
                    store_hl(C2h, C2l, i0x, n0, n1);
                    store_hl(C2h, C2l, i1x, n2, n3);
                    if (C) {
                        *(float2*)(C + i0x) = make_float2(n0, n1);
                        *(float2*)(C + i1x) = make_float2(n2, n3);
                    }
                }
            } else {
                float mu0 = s0 * (1.f / 128.f), mu1 = s1 * (1.f / 128.f);
                float rs0 = rsqrtf(t0 * (1.f / 128.f) - mu0 * mu0 + 1e-5f);
                float rs1 = rsqrtf(t1 * (1.f / 128.f) - mu1 * mu1 + 1e-5f);
                #pragma unroll
                for (int nt = 0; nt < 4; nt++) {
                    int col = bn + wn * 32 + nt * 8 + 2 * lc;
                    float* a = acc[mt][nt];
                    float2 g2 = *(const float2*)(gam + col);
                    float2 be2 = *(const float2*)(bet + col);
                    float w0 = (a[0] - mu0) * rs0 * g2.x + be2.x;
                    float w1 = (a[1] - mu0) * rs0 * g2.y + be2.y;
                    float w2 = (a[2] - mu1) * rs1 * g2.x + be2.x;
                    float w3 = (a[3] - mu1) * rs1 * g2.y + be2.y;
                    size_t i0x = (size_t)row0 * ldc + col, i1x = (size_t)(row0 + 8) * ldc + col;
                    *(float2*)(C + i0x) = make_float2(w0, w1);
                    *(float2*)(C + i1x) = make_float2(w2, w3);
                    if (Ch) {
                        store_hl(Ch, Cl, i0x, w0, w1);
                        store_hl(Ch, Cl, i1x, w2, w3);
                    }
                }
            }
        }
    } else {
        #pragma unroll
        for (int mt = 0; mt < 2; mt++) {
            int row = bm + wm * 32 + mt * 16 + lr;
            #pragma unroll
            for (int nt = 0; nt < 4; nt++) {
                int col = bn + wn * 32 + nt * 8 + 2 * lc;
                float* a = acc[mt][nt];
                size_t i0x = (size_t)row * ldc + col, i1x = (size_t)(row + 8) * ldc + col;
                if (mode == EP_GELU) {
                    store_hl(Ch, Cl, i0x, a[0], a[1]);
                    store_hl(Ch, Cl, i1x, a[2], a[3]);
                } else {
                    *(float2*)(C + i0x) = make_float2(a[0], a[1]);
                    *(float2*)(C + i1x) = make_float2(a[2], a[3]);
                }
            }
        }
    }
}

// ============== M covariance: M[b] += sn^T tn (contract over s) ==============
#define CST 34816
__global__ void __launch_bounds__(256) mcov_mma(
    const __nv_bfloat16* __restrict__ snh, const __nv_bfloat16* __restrict__ snl,
    const __nv_bfloat16* __restrict__ tnh, const __nv_bfloat16* __restrict__ tnl,
    float* __restrict__ M)
{
    extern __shared__ char smem[];
    uint32_t sb = smem_to_u32(smem);
    const int tid = threadIdx.x, lane = tid & 31, wid = tid >> 5;
    const int wm = wid >> 2, wn = wid & 3;
    const int lr = lane >> 2, lc = lane & 3;
    const int b = blockIdx.y, split = blockIdx.x;

    const int r = tid >> 3, q = tid & 7;
    const size_t srow0 = (size_t)b * SS + split * 128;
    const size_t gIdx = (srow0 + r) * 128 + q * 16;
    const __nv_bfloat16 *pSh = snh + gIdx, *pSl = snl + gIdx;
    const __nv_bfloat16 *pTh = tnh + gIdx, *pTl = tnl + gIdx;
    const uint32_t dBase = sb + r * 272 + q * 32;

    float acc[4][4][4];
    #pragma unroll
    for (int i = 0; i < 4; i++)
        #pragma unroll
        for (int j = 0; j < 4; j++)
            #pragma unroll
            for (int k = 0; k < 4; k++) acc[i][j][k] = 0.f;

    {
        uint32_t d = dBase;
        CP16(d, pSh); CP16(d + 16, pSh + 8);
        CP16(d + 8704, pSl); CP16(d + 8704 + 16, pSl + 8);
        CP16(d + 17408, pTh); CP16(d + 17408 + 16, pTh + 8);
        CP16(d + 26112, pTl); CP16(d + 26112 + 16, pTl + 8);
        CP_COMMIT();
    }

    for (int c = 0; c < 4; c++) {
        if (c + 1 < 4) {
            uint32_t d = dBase + ((c + 1) & 1) * CST;
            const size_t co = (size_t)(c + 1) * 32 * 128;
            CP16(d, pSh + co); CP16(d + 16, pSh + co + 8);
            CP16(d + 8704, pSl + co); CP16(d + 8704 + 16, pSl + co + 8);
            CP16(d + 17408, pTh + co); CP16(d + 17408 + 16, pTh + co + 8);
            CP16(d + 26112, pTl + co); CP16(d + 26112 + 16, pTl + co + 8);
            CP_COMMIT();
            CP_WAIT(1);
        } else {
            CP_WAIT(0);
        }
        __syncthreads();
        uint32_t base = sb + (c & 1) * CST;
        #pragma unroll
        for (int ks = 0; ks < 2; ks++) {
            uint32_t ah[4][4], al[4][4], bh[4][2], bl[4][2];
            #pragma unroll
            for (int mt = 0; mt < 4; mt++) {
                int rowk = ks * 16 + (lane & 7) + ((lane >> 4) & 1) * 8;
                int colm = wm * 64 + mt * 16 + ((lane >> 3) & 1) * 8;
                uint32_t addr = base + (uint32_t)(rowk * 272 + colm * 2);
                LDSM4T(ah[mt][0], ah[mt][1], ah[mt][2], ah[mt][3], addr);
                LDSM4T(al[mt][0], al[mt][1], al[mt][2], al[mt][3], addr + 8704);
            }
            #pragma unroll
            for (int nt = 0; nt < 4; nt++) {
                int rowk = ks * 16 + (lane & 15);
                int coln = wn * 32 + nt * 8;
                uint32_t addr = base + 17408 + (uint32_t)(rowk * 272 + coln * 2);
                LDSM2T(bh[nt][0], bh[nt][1], addr);
                LDSM2T(bl[nt][0], bl[nt][1], addr + 8704);
            }
            // 3 passes of 16 independent MMAs
            #pragma unroll
            for (int mt = 0; mt < 4; mt++)
                #pragma unroll
                for (int nt = 0; nt < 4; nt++)
                    MMA_BF16(acc[mt][nt], ah[mt], bh[nt]);
            #pragma unroll
            for (int mt = 0; mt < 4; mt++)
                #pragma unroll
                for (int nt = 0; nt < 4; nt++)
                    MMA_BF16(acc[mt][nt], ah[mt], bl[nt]);
            #pragma unroll
            for (int mt = 0; mt < 4; mt++)
                #pragma unroll
                for (int nt = 0; nt < 4; nt++)
                    MMA_BF16(acc[mt][nt], al[mt], bh[nt]);
        }
        __syncthreads();
    }

    float* Mb = M + (size_t)b * 16384;
    #pragma unroll
    for (int mt = 0; mt < 4; mt++) {
        int row = wm * 64 + mt * 16 + lr;
        #pragma unroll
        for (int nt = 0; nt < 4; nt++) {
            int col = wn * 32 + nt * 8 + 2 * lc;
            atomicAdd(&Mb[(size_t)row * 128 + col], acc[mt][nt][0]);
            atomicAdd(&Mb[(size_t)row * 128 + col + 1], acc[mt][nt][1]);
            atomicAdd(&Mb[(size_t)(row + 8) * 128 + col], acc[mt][nt][2]);
            atomicAdd(&Mb[(size_t)(row + 8) * 128 + col + 1], acc[mt][nt][3]);
        }
    }
}

// ---------------- local windowed causal attention ----------------
__global__ __launch_bounds__(64) void lw_attn_k(const float* __restrict__ qkv,
                                                __nv_bfloat16* __restrict__ Ch,
                                                __nv_bfloat16* __restrict__ Cl)
{
    int g = blockIdx.x, h = blockIdx.y, i = threadIdx.x;
    __shared__ float ks[64][17];
    __shared__ float vs[64][17];
    size_t tbase = (size_t)g * 64;
    const float* kp = qkv + (tbase + i) * 384 + 128 + h * 16;
    const float* vp = kp + 128;
    #pragma unroll
    for (int d = 0; d < 16; d++) { ks[i][d] = kp[d]; vs[i][d] = vp[d]; }
    float q[16];
    const float* qp = qkv + (tbase + i) * 384 + h * 16;
    #pragma unroll
    for (int d = 0; d < 16; d++) q[d] = qp[d];
    __syncthreads();
    float sc[64];
    float mx = -1e30f;
    #pragma unroll
    for (int j = 0; j < 64; j++) {
        float dv = 0.f;
        #pragma unroll
        for (int d = 0; d < 16; d++) dv += q[d] * ks[j][d];
        sc[j] = (j <= i) ? dv * 0.25f : -INFINITY;
        mx = fmaxf(mx, sc[j]);
    }
    float sum = 0.f;
    #pragma unroll
    for (int j = 0; j < 64; j++) { float e = expf(sc[j] - mx); sc[j] = e; sum += e; }
    float o[16] = {};
    #pragma unroll
    for (int j = 0; j < 64; j++) {
        float w = sc[j];
        #pragma unroll
        for (int d = 0; d < 16; d++) o[d] += w * vs[j][d];
    }
    float inv = 1.f / sum;
    size_t ob = (tbase + i) * 128 + h * 16;
    #pragma unroll
    for (int d = 0; d < 16; d += 2)
        store_hl(Ch, Cl, ob + d, o[d] * inv, o[d + 1] * inv);
}

// ---------------- interaction MHA (len = B = 8) ----------------
__global__ __launch_bounds__(64) void int_attn_k(const float* __restrict__ qkv,
                                                 __nv_bfloat16* __restrict__ Ch,
                                                 __nv_bfloat16* __restrict__ Cl)
{
    int s = blockIdx.x, tid = threadIdx.x;
    __shared__ float kvs[8][256];
    for (int idx = tid; idx < 8 * 256; idx += 64) {
        int jb = idx >> 8, c = idx & 255;
        kvs[jb][c] = qkv[((size_t)jb * SS + s) * 384 + 128 + c];
    }
    __syncthreads();
    int h = tid >> 3, qb = tid & 7;
    float q[16];
    const float* qp = qkv + ((size_t)qb * SS + s) * 384 + h * 16;
    #pragma unroll
    for (int d = 0; d < 16; d++) q[d] = qp[d];
    float sc[8];
    float mx = -1e30f;
    #pragma unroll
    for (int jb = 0; jb < 8; jb++) {
        float dv = 0.f;
        #pragma unroll
        for (int d = 0; d < 16; d++) dv += q[d] * kvs[jb][h * 16 + d];
        sc[jb] = dv * 0.25f;
        mx = fmaxf(mx, sc[jb]);
    }
    float sum = 0.f;
    #pragma unroll
    for (int jb = 0; jb < 8; jb++) { float e = expf(sc[jb] - mx); sc[jb] = e; sum += e; }
    float o[16] = {};
    #pragma unroll
    for (int jb = 0; jb < 8; jb++) {
        float w = sc[jb];
        #pragma unroll
        for (int d = 0; d < 16; d++) o[d] += w * kvs[jb][128 + h * 16 + d];
    }
    float inv = 1.f / sum;
    size_t ob = ((size_t)qb * SS + s) * 128 + h * 16;
    #pragma unroll
    for (int d = 0; d < 16; d += 2)
        store_hl(Ch, Cl, ob + d, o[d] * inv, o[d + 1] * inv);
}

extern "C" void kernel_launch(void* const* d_in, const int* in_sizes, int n_in,
                              void* d_out, int out_size)
{
    const float* x        = (const float*)d_in[0];
    const float* sp       = (const float*)d_in[1];
    const float* tp       = (const float*)d_in[2];
    const float* lw_in_b  = (const float*)d_in[4];
    const float* lw_out_b = (const float*)d_in[6];
    const float* spat_b   = (const float*)d_in[8];
    const float* temp_b   = (const float*)d_in[10];
    const float* int_in_b = (const float*)d_in[12];
    const float* int_out_b= (const float*)d_in[14];
    const float* ffn_b1   = (const float*)d_in[16];
    const float* ffn_b2   = (const float*)d_in[18];
    const float* ln1_g    = (const float*)d_in[19];
    const float* ln1_b    = (const float*)d_in[20];
    const float* ln2_g    = (const float*)d_in[21];
    const float* ln2_b    = (const float*)d_in[22];
    float* out = (float*)d_out;

    float* f32 = nullptr;
    __nv_bfloat16* bf = nullptr;
    cudaGetSymbolAddress((void**)&f32, g_f32);
    cudaGetSymbolAddress((void**)&bf, g_bf);

    static cudaStream_t s2 = nullptr;
    static cudaEvent_t evF = nullptr, evJ = nullptr;
    static bool init_done = false;
    if (!init_done) {
        cudaFuncSetAttribute(gemm_mma, cudaFuncAttributeMaxDynamicSharedMemorySize, 2 * GST);
        cudaFuncSetAttribute(mcov_mma, cudaFuncAttributeMaxDynamicSharedMemorySize, 2 * CST);
        cudaStreamCreateWithFlags(&s2, cudaStreamNonBlocking);
        cudaEventCreateWithFlags(&evF, cudaEventDisableTiming);
        cudaEventCreateWithFlags(&evJ, cudaEventDisableTiming);
        init_done = true;
    }

    float* qkv   = f32 + F_QKV;
    float* qkv2  = f32 + F_QKV2;
    float* bufb  = f32 + F_BUFB;
    float* bufc  = f32 + F_BUFC;
    float* snf   = f32 + F_SNF;
    float* bM    = f32 + F_M;
    float* bsim  = f32 + F_SIM;

    #define BH(o) (bf + (o))
    #define BL(o, n) (bf + (o) + (n))
    const unsigned NT = 2097152;

    // ---- fork point ----
    cudaEventRecord(evF, 0);
    cudaStreamWaitEvent(s2, evF, 0);

    // ===== main stream: x-chain =====
    {
        CvtSrc cs;
        cs.cnt = 5;
        cs.p[0] = x;                         cs.n[0] = 2097152; cs.off[0] = H_X;
        cs.p[1] = (const float*)d_in[3];     cs.n[1] = 49152;   cs.off[1] = H_LWIN;
        cs.p[2] = (const float*)d_in[5];     cs.n[2] = 16384;   cs.off[2] = H_LWOUT;
        cs.p[3] = (const float*)d_in[15];    cs.n[3] = 65536;   cs.off[3] = H_FW1;
        cs.p[4] = (const float*)d_in[17];    cs.n[4] = 65536;   cs.off[4] = H_FW2;
        cvt_k<<<296, 256>>>(cs);
    }
    gemm_mma<<<dim3(3, 256), 256, 2 * GST>>>(
        BH(H_X), BL(H_X, NT), nullptr, nullptr, BH(H_LWIN), BL(H_LWIN, 49152),
        lw_in_b, qkv, nullptr, nullptr, nullptr, nullptr, nullptr, nullptr,
        nullptr, nullptr, 128, 384, EP_F32, 0);
    lw_attn_k<<<dim3(256, 8), 64>>>(qkv, BH(H_ATT), BL(H_ATT, NT));
    gemm_mma<<<dim3(1, 256), 256, 2 * GST>>>(
        BH(H_ATT), BL(H_ATT, NT), nullptr, nullptr, BH(H_LWOUT), BL(H_LWOUT, 16384),
        lw_out_b, bufb, BH(H_BUFB), BL(H_BUFB, NT), nullptr, nullptr,
        x, nullptr, ln1_g, ln1_b, 128, 128, EP_LN, 0);
    gemm_mma<<<dim3(4, 256), 256, 2 * GST>>>(
        BH(H_BUFB), BL(H_BUFB, NT), nullptr, nullptr, BH(H_FW1), BL(H_FW1, 65536),
        ffn_b1, nullptr, BH(H_BUFH), BL(H_BUFH, 8388608), nullptr, nullptr,
        nullptr, nullptr, nullptr, nullptr, 128, 512, EP_GELU, 0);
    gemm_mma<<<dim3(1, 256), 256, 2 * GST>>>(
        BH(H_BUFH), BL(H_BUFH, 8388608), nullptr, nullptr, BH(H_FW2), BL(H_FW2, 65536),
        ffn_b2, bufc, nullptr, nullptr, nullptr, nullptr,
        bufb, nullptr, ln2_g, ln2_b, 512, 128, EP_LN2, 0);

    // ===== stream 2: spatio-temporal chain =====
    {
        CvtSrc cs;
        cs.cnt = 6;
        cs.p[0] = sp;                        cs.n[0] = 2097152; cs.off[0] = H_SP;
        cs.p[1] = tp;                        cs.n[1] = 2097152; cs.off[1] = H_TP;
        cs.p[2] = (const float*)d_in[7];     cs.n[2] = 16384;   cs.off[2] = H_SPATW;
        cs.p[3] = (const float*)d_in[9];     cs.n[3] = 16384;   cs.off[3] = H_TEMPW;
        cs.p[4] = (const float*)d_in[11];    cs.n[4] = 49152;   cs.off[4] = H_INTIN;
        cs.p[5] = (const float*)d_in[13];    cs.n[5] = 16384;   cs.off[5] = H_INTOUT;
        cvt_k<<<296, 256, 0, s2>>>(cs);
    }
    zero_k<<<512, 256, 0, s2>>>(bM, 8 * 128 * 128);
    gemm_mma<<<dim3(1, 256), 256, 2 * GST, s2>>>(
        BH(H_SP), BL(H_SP, NT), nullptr, nullptr, BH(H_SPATW), BL(H_SPATW, 16384),
        spat_b, snf, BH(H_SE), BL(H_SE, NT), BH(H_SN), BL(H_SN, NT),
        nullptr, nullptr, nullptr, nullptr, 128, 128, EP_COS, 0);
    gemm_mma<<<dim3(1, 256), 256, 2 * GST, s2>>>(
        BH(H_TP), BL(H_TP, NT), nullptr, nullptr, BH(H_TEMPW), BL(H_TEMPW, 16384),
        temp_b, nullptr, BH(H_TE), BL(H_TE, NT), BH(H_TN), BL(H_TN, NT),
        nullptr, nullptr, nullptr, nullptr, 128, 128, EP_COS, 0);
    mcov_mma<<<dim3(16, 8), 256, 2 * CST, s2>>>(
        BH(H_SN), BL(H_SN, NT), BH(H_TN), BL(H_TN, NT), bM);
    cvtm_k<<<128, 256, 0, s2>>>(bM, BH(H_M), BL(H_M, 131072), 131072);
    gemm_mma<<<dim3(1, 256), 256, 2 * GST, s2>>>(
        BH(H_TN), BL(H_TN, NT), nullptr, nullptr, BH(H_M), BL(H_M, 131072),
        nullptr, bsim, nullptr, nullptr, nullptr, nullptr,
        snf, nullptr, nullptr, nullptr, 128, 0, EP_SIMDOT, 16384);
    gemm_mma<<<dim3(3, 256), 256, 2 * GST, s2>>>(
        BH(H_SE), BL(H_SE, NT), BH(H_TE), BL(H_TE, NT), BH(H_INTIN), BL(H_INTIN, 49152),
        int_in_b, qkv2, nullptr, nullptr, nullptr, nullptr, nullptr, nullptr,
        nullptr, nullptr, 128, 384, EP_F32, 0);
    int_attn_k<<<SS, 64, 0, s2>>>(qkv2, BH(H_ATT2), BL(H_ATT2, NT));
    cudaEventRecord(evJ, s2);

    // ---- join + final ----
    cudaStreamWaitEvent(0, evJ, 0);
    gemm_mma<<<dim3(1, 256), 256, 2 * GST>>>(
        BH(H_ATT2), BL(H_ATT2, NT), nullptr, nullptr, BH(H_INTOUT), BL(H_INTOUT, 16384),
        int_out_b, out, nullptr, nullptr, nullptr, nullptr,
        bufc, bsim, nullptr, nullptr, 128, 128, EP_FINAL, 0);
}

// round 10
// speedup vs baseline: 1.3595x; 1.1607x over previous
#include <cuda_runtime.h>
#include <cuda_bf16.h>
#include <cstdint>
#include <math.h>

#define BB 8
#define SS 2048
#define TT 16384

// ---------------- fp32 scratch ----------------
#define F_QKV  0u
#define F_BUFB 6291456u
#define F_BUFC 8388608u
#define F_SNF  10485760u
#define F_M    12582912u
#define F_SIM  12713984u
#define F_QKV2 12730368u
#define F_TOT  19021824u
__device__ float g_f32[F_TOT];

// ---------------- tf32 scratch (floats holding tf32-rounded values) ----------------
#define T_X      0u
#define T_SP     2097152u
#define T_TP     4194304u
#define T_ATT    6291456u
#define T_BUFB   8388608u
#define T_SE     10485760u
#define T_SN     12582912u
#define T_TE     14680064u
#define T_TN     16777216u
#define T_ATT2   18874368u
#define T_BUFH   20971520u   // 16384*512
#define T_M      29360128u
#define T_LWIN   29491200u
#define T_LWOUT  29540352u
#define T_SPATW  29556736u
#define T_TEMPW  29573120u
#define T_INTIN  29589504u
#define T_INTOUT 29638656u
#define T_FW1    29655040u
#define T_FW2    29720576u
#define T_TOTAL  29786112u
__device__ float g_t[T_TOTAL];

enum { EP_F32 = 0, EP_LN = 1, EP_GELU = 2, EP_LN2 = 3, EP_COS = 4, EP_FINAL = 5, EP_SIMDOT = 6 };

__device__ __forceinline__ uint32_t smem_to_u32(const void* p) {
    uint32_t a;
    asm("{ .reg .u64 t; cvta.to.shared.u64 t, %1; cvt.u32.u64 %0, t; }" : "=r"(a) : "l"(p));
    return a;
}

#define CP16(dst, src) do { \
    unsigned long long _gs = (unsigned long long)__cvta_generic_to_global((const void*)(src)); \
    asm volatile("cp.async.cg.shared.global [%0], [%1], 16;" :: "r"(dst), "l"(_gs)); } while (0)
#define CP_COMMIT() asm volatile("cp.async.commit_group;" ::: "memory")
#define CP_WAIT(n) asm volatile("cp.async.wait_group %0;" :: "n"(n) : "memory")

// tf32 mma: D(16x8) += A(16x8,tf32) * B(8x8,tf32)
#define MMA_TF32(c, a, b) \
    asm volatile("mma.sync.aligned.m16n8k8.row.col.f32.tf32.tf32.f32 " \
        "{%0,%1,%2,%3}, {%4,%5,%6,%7}, {%8,%9}, {%0,%1,%2,%3};" \
        : "+f"((c)[0]), "+f"((c)[1]), "+f"((c)[2]), "+f"((c)[3]) \
        : "r"((a)[0]), "r"((a)[1]), "r"((a)[2]), "r"((a)[3]), "r"((b)[0]), "r"((b)[1]))

__device__ __forceinline__ uint32_t tf32b(float x) {
    uint32_t u;
    asm("cvt.rna.tf32.f32 %0, %1;" : "=r"(u) : "f"(x));
    return u;
}
__device__ __forceinline__ float tf32r(float x) { return __uint_as_float(tf32b(x)); }

__device__ __forceinline__ float gelu_f(float v) {
    return 0.5f * v * (1.0f + erff(v * 0.70710678118654752f));
}

// ============== tf32 rounding conversion ==============
struct CvtSrc { const float* p[6]; int n[6]; unsigned off[6]; int cnt; };
__global__ void __launch_bounds__(256) cvt_k(CvtSrc s)
{
    int stride = gridDim.x * blockDim.x;
    int t = blockIdx.x * blockDim.x + threadIdx.x;
    for (int seg = 0; seg < s.cnt; seg++) {
        const float4* src = (const float4*)s.p[seg];
        float4* dst = (float4*)(g_t + s.off[seg]);
        int m = s.n[seg] >> 2;
        for (int i = t; i < m; i += stride) {
            float4 v = src[i];
            v.x = tf32r(v.x); v.y = tf32r(v.y); v.z = tf32r(v.z); v.w = tf32r(v.w);
            dst[i] = v;
        }
    }
}

__global__ void __launch_bounds__(256) cvtm_k(const float* __restrict__ src,
                                              float* __restrict__ dst, int n)
{
    int t = blockIdx.x * blockDim.x + threadIdx.x;
    int m = n >> 2;
    for (int i = t; i < m; i += gridDim.x * blockDim.x) {
        float4 v = ((const float4*)src)[i];
        v.x = tf32r(v.x); v.y = tf32r(v.y); v.z = tf32r(v.z); v.w = tf32r(v.w);
        ((float4*)dst)[i] = v;
    }
}

__global__ void zero_k(float* p, int n)
{
    int i = blockIdx.x * 256 + threadIdx.x;
    if (i < n) p[i] = 0.f;
}

// ============== generic tf32 GEMM: C[M,N] = A @ W^T ==============
// Tile 64(M) x 128(N), 256 threads = 8 warps (2 wm x 4 wn), warp tile 32x32.
// smem stage (27648B): A +0 (64 rows x 36 floats), B +9216 (128 rows x 36 floats).
#define GSTT 27648
__global__ void __launch_bounds__(256, 3) gemm_tf(
    const float* __restrict__ A, const float* __restrict__ A2,
    const float* __restrict__ W,
    const float* __restrict__ bias, float* __restrict__ C,
    float* __restrict__ Ct, float* __restrict__ C2t,
    const float* __restrict__ R, const float* __restrict__ rs,
    const float* __restrict__ gam, const float* __restrict__ bet,
    int K, int ldc, int mode, int batchW)
{
    extern __shared__ char smem[];
    float* sf = (float*)smem;
    uint32_t sb = smem_to_u32(smem);
    const int tid = threadIdx.x, lane = tid & 31, wid = tid >> 5;
    const int wm = wid >> 2, wn = wid & 3;
    const int lr = lane >> 2, lc = lane & 3;
    const int bm = blockIdx.y * 64, bn = blockIdx.x * 128;

    const float* Au = (A2 && bn > 0) ? A2 : A;
    if (batchW) W += (size_t)(bm >> 11) * (size_t)batchW;

    // A loader: 64 rows x 8 quarters(16B); 2 per thread
    // B loader: 128 rows x 8 quarters; 4 per thread
    const int nch = K >> 5;

    float acc[2][4][4];
    #pragma unroll
    for (int i = 0; i < 2; i++)
        #pragma unroll
        for (int j = 0; j < 4; j++)
            #pragma unroll
            for (int k = 0; k < 4; k++) acc[i][j][k] = 0.f;

    // prologue
    #pragma unroll
    for (int j = 0; j < 2; j++) {
        int id = tid + j * 256;
        int row = id >> 3, q = id & 7;
        CP16(sb + row * 144 + q * 16, Au + (size_t)(bm + row) * K + q * 4);
    }
    #pragma unroll
    for (int j = 0; j < 4; j++) {
        int id = tid + j * 256;
        int row = id >> 3, q = id & 7;
        CP16(sb + 9216 + row * 144 + q * 16, W + (size_t)(bn + row) * K + q * 4);
    }
    CP_COMMIT();

    for (int c = 0; c < nch; c++) {
        if (c + 1 < nch) {
            uint32_t stg = ((c + 1) & 1) * GSTT;
            const int k0 = (c + 1) * 32;
            #pragma unroll
            for (int j = 0; j < 2; j++) {
                int id = tid + j * 256;
                int row = id >> 3, q = id & 7;
                CP16(sb + stg + row * 144 + q * 16, Au + (size_t)(bm + row) * K + k0 + q * 4);
            }
            #pragma unroll
            for (int j = 0; j < 4; j++) {
                int id = tid + j * 256;
                int row = id >> 3, q = id & 7;
                CP16(sb + stg + 9216 + row * 144 + q * 16, W + (size_t)(bn + row) * K + k0 + q * 4);
            }
            CP_COMMIT();
            CP_WAIT(1);
        } else {
            CP_WAIT(0);
        }
        __syncthreads();
        const float* tA = sf + (c & 1) * (GSTT / 4);
        const float* tB = tA + 2304;  // 9216B
        #pragma unroll
        for (int ks = 0; ks < 4; ks++) {
            const int ko = ks * 8;
            uint32_t af[2][4], bf[4][2];
            #pragma unroll
            for (int mt = 0; mt < 2; mt++) {
                int r0 = (wm * 32 + mt * 16 + lr) * 36 + ko + lc;
                af[mt][0] = __float_as_uint(tA[r0]);
                af[mt][1] = __float_as_uint(tA[r0 + 8 * 36]);
                af[mt][2] = __float_as_uint(tA[r0 + 4]);
                af[mt][3] = __float_as_uint(tA[r0 + 8 * 36 + 4]);
            }
            #pragma unroll
            for (int nt = 0; nt < 4; nt++) {
                int n0 = (wn * 32 + nt * 8 + lr) * 36 + ko + lc;
                bf[nt][0] = __float_as_uint(tB[n0]);
                bf[nt][1] = __float_as_uint(tB[n0 + 4]);
            }
            #pragma unroll
            for (int mt = 0; mt < 2; mt++)
                #pragma unroll
                for (int nt = 0; nt < 4; nt++)
                    MMA_TF32(acc[mt][nt], af[mt], bf[nt]);
        }
        __syncthreads();
    }

    // ---------------- epilogues ----------------
    if (mode == EP_SIMDOT) {
        float* simS = (float*)smem;
        if (tid < 64) simS[tid] = 0.f;
        __syncthreads();
        #pragma unroll
        for (int mt = 0; mt < 2; mt++) {
            int row0 = bm + wm * 32 + mt * 16 + lr;
            float d0 = 0.f, d1 = 0.f;
            #pragma unroll
            for (int nt = 0; nt < 4; nt++) {
                int col = bn + wn * 32 + nt * 8 + 2 * lc;
                float2 s0 = *(const float2*)(R + (size_t)row0 * 128 + col);
                float2 s1 = *(const float2*)(R + (size_t)(row0 + 8) * 128 + col);
                d0 += acc[mt][nt][0] * s0.x + acc[mt][nt][1] * s0.y;
                d1 += acc[mt][nt][2] * s1.x + acc[mt][nt][3] * s1.y;
            }
            d0 += __shfl_xor_sync(0xffffffffu, d0, 1);
            d0 += __shfl_xor_sync(0xffffffffu, d0, 2);
            d1 += __shfl_xor_sync(0xffffffffu, d1, 1);
            d1 += __shfl_xor_sync(0xffffffffu, d1, 2);
            if (lc == 0) {
                atomicAdd(&simS[wm * 32 + mt * 16 + lr], d0);
                atomicAdd(&simS[wm * 32 + mt * 16 + lr + 8], d1);
            }
        }
        __syncthreads();
        if (tid < 64) C[bm + tid] = simS[tid] * (1.f / 2048.f);
        return;
    }

    #pragma unroll
    for (int mt = 0; mt < 2; mt++) {
        int row = bm + wm * 32 + mt * 16 + lr;
        #pragma unroll
        for (int nt = 0; nt < 4; nt++) {
            int col = bn + wn * 32 + nt * 8 + 2 * lc;
            float2 b2 = *(const float2*)(bias + col);
            float* a = acc[mt][nt];
            a[0] += b2.x; a[1] += b2.y; a[2] += b2.x; a[3] += b2.y;
            if (mode == EP_LN || mode == EP_LN2) {
                float2 r0 = *(const float2*)(R + (size_t)row * ldc + col);
                float2 r1 = *(const float2*)(R + (size_t)(row + 8) * ldc + col);
                a[0] += r0.x; a[1] += r0.y; a[2] += r1.x; a[3] += r1.y;
            } else if (mode == EP_GELU) {
                a[0] = gelu_f(a[0]); a[1] = gelu_f(a[1]);
                a[2] = gelu_f(a[2]); a[3] = gelu_f(a[3]);
            } else if (mode == EP_FINAL) {
                float2 r0 = *(const float2*)(R + (size_t)row * ldc + col);
                float2 r1 = *(const float2*)(R + (size_t)(row + 8) * ldc + col);
                float sc0 = rs[row], sc1 = rs[row + 8];
                a[0] = r0.x + sc0 * a[0]; a[1] = r0.y + sc0 * a[1];
                a[2] = r1.x + sc1 * a[2]; a[3] = r1.y + sc1 * a[3];
            }
        }
    }

    if (mode == EP_LN || mode == EP_LN2 || mode == EP_COS) {
        float* ps = (float*)smem;        // [64][4]
        float* ps2 = ps + 256;
        #pragma unroll
        for (int mt = 0; mt < 2; mt++) {
            float p0 = 0.f, p1 = 0.f, q0 = 0.f, q1 = 0.f;
            #pragma unroll
            for (int nt = 0; nt < 4; nt++) {
                float* a = acc[mt][nt];
                p0 += a[0] + a[1]; q0 += a[0] * a[0] + a[1] * a[1];
                p1 += a[2] + a[3]; q1 += a[2] * a[2] + a[3] * a[3];
            }
            p0 += __shfl_xor_sync(0xffffffffu, p0, 1); p0 += __shfl_xor_sync(0xffffffffu, p0, 2);
            p1 += __shfl_xor_sync(0xffffffffu, p1, 1); p1 += __shfl_xor_sync(0xffffffffu, p1, 2);
            q0 += __shfl_xor_sync(0xffffffffu, q0, 1); q0 += __shfl_xor_sync(0xffffffffu, q0, 2);
            q1 += __shfl_xor_sync(0xffffffffu, q1, 1); q1 += __shfl_xor_sync(0xffffffffu, q1, 2);
            if (lc == 0) {
                int r0l = wm * 32 + mt * 16 + lr;
                ps[r0l * 4 + wn] = p0; ps2[r0l * 4 + wn] = q0;
                ps[(r0l + 8) * 4 + wn] = p1; ps2[(r0l + 8) * 4 + wn] = q1;
            }
        }
        __syncthreads();
        #pragma unroll
        for (int mt = 0; mt < 2; mt++) {
            int r0l = wm * 32 + mt * 16 + lr;
            float s0 = 0.f, t0 = 0.f, s1 = 0.f, t1 = 0.f;
            #pragma unroll
            for (int w4 = 0; w4 < 4; w4++) {
                s0 += ps[r0l * 4 + w4]; t0 += ps2[r0l * 4 + w4];
                s1 += ps[(r0l + 8) * 4 + w4]; t1 += ps2[(r0l + 8) * 4 + w4];
            }
            int row0 = bm + r0l;
            if (mode == EP_COS) {
                float i0 = 1.f / fmaxf(sqrtf(t0), 1e-8f);
                float i1 = 1.f / fmaxf(sqrtf(t1), 1e-8f);
                #pragma unroll
                for (int nt = 0; nt < 4; nt++) {
                    int col = bn + wn * 32 + nt * 8 + 2 * lc;
                    float* a = acc[mt][nt];
                    size_t i0x = (size_t)row0 * ldc + col, i1x = (size_t)(row0 + 8) * ldc + col;
                    *(float2*)(Ct + i0x) = make_float2(tf32r(a[0]), tf32r(a[1]));
                    *(float2*)(Ct + i1x) = make_float2(tf32r(a[2]), tf32r(a[3]));
                    float n0 = a[0] * i0, n1 = a[1] * i0, n2 = a[2] * i1, n3 = a[3] * i1;
                    *(float2*)(C2t + i0x) = make_float2(tf32r(n0), tf32r(n1));
                    *(float2*)(C2t + i1x) = make_float2(tf32r(n2), tf32r(n3));
                    if (C) {
                        *(float2*)(C + i0x) = make_float2(n0, n1);
                        *(float2*)(C + i1x) = make_float2(n2, n3);
                    }
                }
            } else {
                float mu0 = s0 * (1.f / 128.f), mu1 = s1 * (1.f / 128.f);
                float rs0 = rsqrtf(t0 * (1.f / 128.f) - mu0 * mu0 + 1e-5f);
                float rs1 = rsqrtf(t1 * (1.f / 128.f) - mu1 * mu1 + 1e-5f);
                #pragma unroll
                for (int nt = 0; nt < 4; nt++) {
                    int col = bn + wn * 32 + nt * 8 + 2 * lc;
                    float* a = acc[mt][nt];
                    float2 g2 = *(const float2*)(gam + col);
                    float2 be2 = *(const float2*)(bet + col);
                    float w0 = (a[0] - mu0) * rs0 * g2.x + be2.x;
                    float w1 = (a[1] - mu0) * rs0 * g2.y + be2.y;
                    float w2 = (a[2] - mu1) * rs1 * g2.x + be2.x;
                    float w3 = (a[3] - mu1) * rs1 * g2.y + be2.y;
                    size_t i0x = (size_t)row0 * ldc + col, i1x = (size_t)(row0 + 8) * ldc + col;
                    *(float2*)(C + i0x) = make_float2(w0, w1);
                    *(float2*)(C + i1x) = make_float2(w2, w3);
                    if (Ct) {
                        *(float2*)(Ct + i0x) = make_float2(tf32r(w0), tf32r(w1));
                        *(float2*)(Ct + i1x) = make_float2(tf32r(w2), tf32r(w3));
                    }
                }
            }
        }
    } else {
        #pragma unroll
        for (int mt = 0; mt < 2; mt++) {
            int row = bm + wm * 32 + mt * 16 + lr;
            #pragma unroll
            for (int nt = 0; nt < 4; nt++) {
                int col = bn + wn * 32 + nt * 8 + 2 * lc;
                float* a = acc[mt][nt];
                size_t i0x = (size_t)row * ldc + col, i1x = (size_t)(row + 8) * ldc + col;
                if (mode == EP_GELU) {
                    *(float2*)(Ct + i0x) = make_float2(tf32r(a[0]), tf32r(a[1]));
                    *(float2*)(Ct + i1x) = make_float2(tf32r(a[2]), tf32r(a[3]));
                } else {
                    *(float2*)(C + i0x) = make_float2(a[0], a[1]);
                    *(float2*)(C + i1x) = make_float2(a[2], a[3]);
                }
            }
        }
    }
}

// ============== M covariance: M[b] += sn^T tn (contract over s) ==============
// Tiles stored [s][d]: 32 rows x 132 floats (528B stride). A-side read transposed.
#define CSTT 33792
__global__ void __launch_bounds__(256, 2) mcov_tf(
    const float* __restrict__ sn, const float* __restrict__ tn, float* __restrict__ M)
{
    extern __shared__ char smem[];
    float* sf = (float*)smem;
    uint32_t sb = smem_to_u32(smem);
    const int tid = threadIdx.x, lane = tid & 31, wid = tid >> 5;
    const int wm = wid >> 2, wn = wid & 3;
    const int lr = lane >> 2, lc = lane & 3;
    const int b = blockIdx.y, split = blockIdx.x;
    const size_t srow0 = (size_t)b * SS + split * 128;

    float acc[4][4][4];
    #pragma unroll
    for (int i = 0; i < 4; i++)
        #pragma unroll
        for (int j = 0; j < 4; j++)
            #pragma unroll
            for (int k = 0; k < 4; k++) acc[i][j][k] = 0.f;

    // loaders: 32 s-rows x 32 quarters per tensor; 4/thread each
    #pragma unroll
    for (int j = 0; j < 4; j++) {
        int id = tid + j * 256;
        int row = id >> 5, q = id & 31;
        CP16(sb + row * 528 + q * 16, sn + (srow0 + row) * 128 + q * 4);
        CP16(sb + 16896 + row * 528 + q * 16, tn + (srow0 + row) * 128 + q * 4);
    }
    CP_COMMIT();

    for (int c = 0; c < 4; c++) {
        if (c + 1 < 4) {
            uint32_t stg = ((c + 1) & 1) * CSTT;
            const size_t so = srow0 + (size_t)(c + 1) * 32;
            #pragma unroll
            for (int j = 0; j < 4; j++) {
                int id = tid + j * 256;
                int row = id >> 5, q = id & 31;
                CP16(sb + stg + row * 528 + q * 16, sn + (so + row) * 128 + q * 4);
                CP16(sb + stg + 16896 + row * 528 + q * 16, tn + (so + row) * 128 + q * 4);
            }
            CP_COMMIT();
            CP_WAIT(1);
        } else {
            CP_WAIT(0);
        }
        __syncthreads();
        const float* tS = sf + (c & 1) * (CSTT / 4);
        const float* tT = tS + 4224;  // 16896B
        #pragma unroll
        for (int ks = 0; ks < 4; ks++) {
            const int ko = ks * 8;
            uint32_t af[4][4], bf[4][2];
            #pragma unroll
            for (int mt = 0; mt < 4; mt++) {
                int d0 = wm * 64 + mt * 16 + lr;
                af[mt][0] = __float_as_uint(tS[(ko + lc) * 132 + d0]);
                af[mt][1] = __float_as_uint(tS[(ko + lc) * 132 + d0 + 8]);
                af[mt][2] = __float_as_uint(tS[(ko + lc + 4) * 132 + d0]);
                af[mt][3] = __float_as_uint(tS[(ko + lc + 4) * 132 + d0 + 8]);
            }
            #pragma unroll
            for (int nt = 0; nt < 4; nt++) {
                int e0 = wn * 32 + nt * 8 + lr;
                bf[nt][0] = __float_as_uint(tT[(ko + lc) * 132 + e0]);
                bf[nt][1] = __float_as_uint(tT[(ko + lc + 4) * 132 + e0]);
            }
            #pragma unroll
            for (int mt = 0; mt < 4; mt++)
                #pragma unroll
                for (int nt = 0; nt < 4; nt++)
                    MMA_TF32(acc[mt][nt], af[mt], bf[nt]);
        }
        __syncthreads();
    }

    float* Mb = M + (size_t)b * 16384;
    #pragma unroll
    for (int mt = 0; mt < 4; mt++) {
        int row = wm * 64 + mt * 16 + lr;
        #pragma unroll
        for (int nt = 0; nt < 4; nt++) {
            int col = wn * 32 + nt * 8 + 2 * lc;
            atomicAdd(&Mb[(size_t)row * 128 + col], acc[mt][nt][0]);
            atomicAdd(&Mb[(size_t)row * 128 + col + 1], acc[mt][nt][1]);
            atomicAdd(&Mb[(size_t)(row + 8) * 128 + col], acc[mt][nt][2]);
            atomicAdd(&Mb[(size_t)(row + 8) * 128 + col + 1], acc[mt][nt][3]);
        }
    }
}

// ---------------- local windowed causal attention (writes tf32) ----------------
__global__ __launch_bounds__(64) void lw_attn_k(const float* __restrict__ qkv,
                                                float* __restrict__ Ct)
{
    int g = blockIdx.x, h = blockIdx.y, i = threadIdx.x;
    __shared__ float ks[64][17];
    __shared__ float vs[64][17];
    size_t tbase = (size_t)g * 64;
    const float* kp = qkv + (tbase + i) * 384 + 128 + h * 16;
    const float* vp = kp + 128;
    #pragma unroll
    for (int d = 0; d < 16; d++) { ks[i][d] = kp[d]; vs[i][d] = vp[d]; }
    float q[16];
    const float* qp = qkv + (tbase + i) * 384 + h * 16;
    #pragma unroll
    for (int d = 0; d < 16; d++) q[d] = qp[d];
    __syncthreads();
    float sc[64];
    float mx = -1e30f;
    #pragma unroll
    for (int j = 0; j < 64; j++) {
        float dv = 0.f;
        #pragma unroll
        for (int d = 0; d < 16; d++) dv += q[d] * ks[j][d];
        sc[j] = (j <= i) ? dv * 0.25f : -INFINITY;
        mx = fmaxf(mx, sc[j]);
    }
    float sum = 0.f;
    #pragma unroll
    for (int j = 0; j < 64; j++) { float e = expf(sc[j] - mx); sc[j] = e; sum += e; }
    float o[16] = {};
    #pragma unroll
    for (int j = 0; j < 64; j++) {
        float w = sc[j];
        #pragma unroll
        for (int d = 0; d < 16; d++) o[d] += w * vs[j][d];
    }
    float inv = 1.f / sum;
    float* op = Ct + (tbase + i) * 128 + h * 16;
    #pragma unroll
    for (int d = 0; d < 16; d++) op[d] = tf32r(o[d] * inv);
}

// ---------------- interaction MHA (len = B = 8), writes tf32 ----------------
__global__ __launch_bounds__(64) void int_attn_k(const float* __restrict__ qkv,
                                                 float* __restrict__ Ct)
{
    int s = blockIdx.x, tid = threadIdx.x;
    __shared__ float kvs[8][256];
    for (int idx = tid; idx < 8 * 256; idx += 64) {
        int jb = idx >> 8, c = idx & 255;
        kvs[jb][c] = qkv[((size_t)jb * SS + s) * 384 + 128 + c];
    }
    __syncthreads();
    int h = tid >> 3, qb = tid & 7;
    float q[16];
    const float* qp = qkv + ((size_t)qb * SS + s) * 384 + h * 16;
    #pragma unroll
    for (int d = 0; d < 16; d++) q[d] = qp[d];
    float sc[8];
    float mx = -1e30f;
    #pragma unroll
    for (int jb = 0; jb < 8; jb++) {
        float dv = 0.f;
        #pragma unroll
        for (int d = 0; d < 16; d++) dv += q[d] * kvs[jb][h * 16 + d];
        sc[jb] = dv * 0.25f;
        mx = fmaxf(mx, sc[jb]);
    }
    float sum = 0.f;
    #pragma unroll
    for (int jb = 0; jb < 8; jb++) { float e = expf(sc[jb] - mx); sc[jb] = e; sum += e; }
    float o[16] = {};
    #pragma unroll
    for (int jb = 0; jb < 8; jb++) {
        float w = sc[jb];
        #pragma unroll
        for (int d = 0; d < 16; d++) o[d] += w * kvs[jb][128 + h * 16 + d];
    }
    float inv = 1.f / sum;
    float* op = Ct + ((size_t)qb * SS + s) * 128 + h * 16;
    #pragma unroll
    for (int d = 0; d < 16; d++) op[d] = tf32r(o[d] * inv);
}

extern "C" void kernel_launch(void* const* d_in, const int* in_sizes, int n_in,
                              void* d_out, int out_size)
{
    const float* x        = (const float*)d_in[0];
    const float* sp       = (const float*)d_in[1];
    const float* tp       = (const float*)d_in[2];
    const float* lw_in_b  = (const float*)d_in[4];
    const float* lw_out_b = (const float*)d_in[6];
    const float* spat_b   = (const float*)d_in[8];
    const float* temp_b   = (const float*)d_in[10];
    const float* int_in_b = (const float*)d_in[12];
    const float* int_out_b= (const float*)d_in[14];
    const float* ffn_b1   = (const float*)d_in[16];
    const float* ffn_b2   = (const float*)d_in[18];
    const float* ln1_g    = (const float*)d_in[19];
    const float* ln1_b    = (const float*)d_in[20];
    const float* ln2_g    = (const float*)d_in[21];
    const float* ln2_b    = (const float*)d_in[22];
    float* out = (float*)d_out;

    float* f32 = nullptr;
    float* tb = nullptr;
    cudaGetSymbolAddress((void**)&f32, g_f32);
    cudaGetSymbolAddress((void**)&tb, g_t);

    static cudaStream_t s2 = nullptr;
    static cudaEvent_t evF = nullptr, evJ = nullptr;
    static bool init_done = false;
    if (!init_done) {
        cudaFuncSetAttribute(gemm_tf, cudaFuncAttributeMaxDynamicSharedMemorySize, 2 * GSTT);
        cudaFuncSetAttribute(mcov_tf, cudaFuncAttributeMaxDynamicSharedMemorySize, 2 * CSTT);
        cudaStreamCreateWithFlags(&s2, cudaStreamNonBlocking);
        cudaEventCreateWithFlags(&evF, cudaEventDisableTiming);
        cudaEventCreateWithFlags(&evJ, cudaEventDisableTiming);
        init_done = true;
    }

    float* qkv   = f32 + F_QKV;
    float* qkv2  = f32 + F_QKV2;
    float* bufb  = f32 + F_BUFB;
    float* bufc  = f32 + F_BUFC;
    float* snf   = f32 + F_SNF;
    float* bM    = f32 + F_M;
    float* bsim  = f32 + F_SIM;

    #define TB(o) (tb + (o))

    // ---- fork ----
    cudaEventRecord(evF, 0);
    cudaStreamWaitEvent(s2, evF, 0);

    // ===== main stream: x-chain =====
    {
        CvtSrc cs;
        cs.cnt = 5;
        cs.p[0] = x;                      cs.n[0] = 2097152; cs.off[0] = T_X;
        cs.p[1] = (const float*)d_in[3];  cs.n[1] = 49152;   cs.off[1] = T_LWIN;
        cs.p[2] = (const float*)d_in[5];  cs.n[2] = 16384;   cs.off[2] = T_LWOUT;
        cs.p[3] = (const float*)d_in[15]; cs.n[3] = 65536;   cs.off[3] = T_FW1;
        cs.p[4] = (const float*)d_in[17]; cs.n[4] = 65536;   cs.off[4] = T_FW2;
        cvt_k<<<296, 256>>>(cs);
    }
    gemm_tf<<<dim3(3, 256), 256, 2 * GSTT>>>(
        TB(T_X), nullptr, TB(T_LWIN), lw_in_b, qkv, nullptr, nullptr,
        nullptr, nullptr, nullptr, nullptr, 128, 384, EP_F32, 0);
    lw_attn_k<<<dim3(256, 8), 64>>>(qkv, TB(T_ATT));
    gemm_tf<<<dim3(1, 256), 256, 2 * GSTT>>>(
        TB(T_ATT), nullptr, TB(T_LWOUT), lw_out_b, bufb, TB(T_BUFB), nullptr,
        x, nullptr, ln1_g, ln1_b, 128, 128, EP_LN, 0);
    gemm_tf<<<dim3(4, 256), 256, 2 * GSTT>>>(
        TB(T_BUFB), nullptr, TB(T_FW1), ffn_b1, nullptr, TB(T_BUFH), nullptr,
        nullptr, nullptr, nullptr, nullptr, 128, 512, EP_GELU, 0);
    gemm_tf<<<dim3(1, 256), 256, 2 * GSTT>>>(
        TB(T_BUFH), nullptr, TB(T_FW2), ffn_b2, bufc, nullptr, nullptr,
        bufb, nullptr, ln2_g, ln2_b, 512, 128, EP_LN2, 0);

    // ===== stream 2: spatio-temporal chain =====
    {
        CvtSrc cs;
        cs.cnt = 6;
        cs.p[0] = sp;                     cs.n[0] = 2097152; cs.off[0] = T_SP;
        cs.p[1] = tp;                     cs.n[1] = 2097152; cs.off[1] = T_TP;
        cs.p[2] = (const float*)d_in[7];  cs.n[2] = 16384;   cs.off[2] = T_SPATW;
        cs.p[3] = (const float*)d_in[9];  cs.n[3] = 16384;   cs.off[3] = T_TEMPW;
        cs.p[4] = (const float*)d_in[11]; cs.n[4] = 49152;   cs.off[4] = T_INTIN;
        cs.p[5] = (const float*)d_in[13]; cs.n[5] = 16384;   cs.off[5] = T_INTOUT;
        cvt_k<<<296, 256, 0, s2>>>(cs);
    }
    zero_k<<<512, 256, 0, s2>>>(bM, 8 * 128 * 128);
    gemm_tf<<<dim3(1, 256), 256, 2 * GSTT, s2>>>(
        TB(T_SP), nullptr, TB(T_SPATW), spat_b, snf, TB(T_SE), TB(T_SN),
        nullptr, nullptr, nullptr, nullptr, 128, 128, EP_COS, 0);
    gemm_tf<<<dim3(1, 256), 256, 2 * GSTT, s2>>>(
        TB(T_TP), nullptr, TB(T_TEMPW), temp_b, nullptr, TB(T_TE), TB(T_TN),
        nullptr, nullptr, nullptr, nullptr, 128, 128, EP_COS, 0);
    mcov_tf<<<dim3(16, 8), 256, 2 * CSTT, s2>>>(TB(T_SN), TB(T_TN), bM);
    cvtm_k<<<128, 256, 0, s2>>>(bM, TB(T_M), 131072);
    gemm_tf<<<dim3(1, 256), 256, 2 * GSTT, s2>>>(
        TB(T_TN), nullptr, TB(T_M), nullptr, bsim, nullptr, nullptr,
        snf, nullptr, nullptr, nullptr, 128, 0, EP_SIMDOT, 16384);
    gemm_tf<<<dim3(3, 256), 256, 2 * GSTT, s2>>>(
        TB(T_SE), TB(T_TE), TB(T_INTIN), int_in_b, qkv2, nullptr, nullptr,
        nullptr, nullptr, nullptr, nullptr, 128, 384, EP_F32, 0);
    int_attn_k<<<SS, 64, 0, s2>>>(qkv2, TB(T_ATT2));
    cudaEventRecord(evJ, s2);

    // ---- join + final ----
    cudaStreamWaitEvent(0, evJ, 0);
    gemm_tf<<<dim3(1, 256), 256, 2 * GSTT>>>(
        TB(T_ATT2), nullptr, TB(T_INTOUT), int_out_b, out, nullptr, nullptr,
        bufc, bsim, nullptr, nullptr, 128, 128, EP_FINAL, 0);
}

// round 11
// speedup vs baseline: 1.5037x; 1.1061x over previous
#include <cuda_runtime.h>
#include <cstdint>
#include <math.h>

#define BB 8
#define SS 2048
#define TT 16384

// ---------------- fp32 scratch ----------------
#define F_QKV  0u            // 16384*384
#define F_QKV2 6291456u      // 16384*384
#define F_ATT  12582912u     // 16384*128
#define F_ATT2 14680064u
#define F_BUFB 16777216u
#define F_BUFH 18874368u     // 16384*512
#define F_BUFC 27262976u
#define F_SE   29360128u
#define F_SN   31457280u
#define F_TE   33554432u
#define F_TN   35651584u
#define F_M    37748736u     // 8*128*128
#define F_SIM  37879808u     // 16384
#define F_TOT  37896192u
__device__ float g_f32[F_TOT];

enum { EP_F32 = 0, EP_LN = 1, EP_GELU = 2, EP_LN2 = 3, EP_COS = 4, EP_FINAL = 5, EP_SIMDOT = 6 };

__device__ __forceinline__ uint32_t smem_to_u32(const void* p) {
    uint32_t a;
    asm("{ .reg .u64 t; cvta.to.shared.u64 t, %1; cvt.u32.u64 %0, t; }" : "=r"(a) : "l"(p));
    return a;
}

#define CP16(dst, src) do { \
    unsigned long long _gs = (unsigned long long)__cvta_generic_to_global((const void*)(src)); \
    asm volatile("cp.async.cg.shared.global [%0], [%1], 16;" :: "r"(dst), "l"(_gs)); } while (0)
#define CP_COMMIT() asm volatile("cp.async.commit_group;" ::: "memory")
#define CP_WAIT(n) asm volatile("cp.async.wait_group %0;" :: "n"(n) : "memory")

// tf32 mma: D(16x8) += A(16x8) * B(8x8); raw f32 regs are truncated to tf32 by HW
#define MMA_TF32(c, a, b) \
    asm volatile("mma.sync.aligned.m16n8k8.row.col.f32.tf32.tf32.f32 " \
        "{%0,%1,%2,%3}, {%4,%5,%6,%7}, {%8,%9}, {%0,%1,%2,%3};" \
        : "+f"((c)[0]), "+f"((c)[1]), "+f"((c)[2]), "+f"((c)[3]) \
        : "r"((a)[0]), "r"((a)[1]), "r"((a)[2]), "r"((a)[3]), "r"((b)[0]), "r"((b)[1]))

__device__ __forceinline__ float gelu_f(float v) {
    return 0.5f * v * (1.0f + erff(v * 0.70710678118654752f));
}

__global__ void zero_k(float* p, int n)
{
    int i = blockIdx.x * 256 + threadIdx.x;
    if (i < n) p[i] = 0.f;
}

// ============== generic tf32 GEMM: C[M,N] = A @ W^T ==============
// Tile 64(M) x 128(N), 256 threads = 8 warps (2 wm x 4 wn), warp tile 32x32.
// smem stage (27648B): A +0 (64 rows x 36 floats), B +9216 (128 rows x 36 floats).
#define GSTT 27648
__global__ void __launch_bounds__(256, 3) gemm_tf(
    const float* __restrict__ A, const float* __restrict__ A2,
    const float* __restrict__ W,
    const float* __restrict__ bias, float* __restrict__ C,
    float* __restrict__ Ct,
    const float* __restrict__ R, const float* __restrict__ rs,
    const float* __restrict__ gam, const float* __restrict__ bet,
    int K, int ldc, int mode, int batchW)
{
    extern __shared__ char smem[];
    float* sf = (float*)smem;
    uint32_t sb = smem_to_u32(smem);
    const int tid = threadIdx.x, lane = tid & 31, wid = tid >> 5;
    const int wm = wid >> 2, wn = wid & 3;
    const int lr = lane >> 2, lc = lane & 3;
    const int bm = blockIdx.y * 64, bn = blockIdx.x * 128;

    const float* Au = (A2 && bn > 0) ? A2 : A;
    if (batchW) W += (size_t)(bm >> 11) * (size_t)batchW;

    const int nch = K >> 5;

    float acc[2][4][4];
    #pragma unroll
    for (int i = 0; i < 2; i++)
        #pragma unroll
        for (int j = 0; j < 4; j++)
            #pragma unroll
            for (int k = 0; k < 4; k++) acc[i][j][k] = 0.f;

    // prologue
    #pragma unroll
    for (int j = 0; j < 2; j++) {
        int id = tid + j * 256;
        int row = id >> 3, q = id & 7;
        CP16(sb + row * 144 + q * 16, Au + (size_t)(bm + row) * K + q * 4);
    }
    #pragma unroll
    for (int j = 0; j < 4; j++) {
        int id = tid + j * 256;
        int row = id >> 3, q = id & 7;
        CP16(sb + 9216 + row * 144 + q * 16, W + (size_t)(bn + row) * K + q * 4);
    }
    CP_COMMIT();

    for (int c = 0; c < nch; c++) {
        if (c + 1 < nch) {
            uint32_t stg = ((c + 1) & 1) * GSTT;
            const int k0 = (c + 1) * 32;
            #pragma unroll
            for (int j = 0; j < 2; j++) {
                int id = tid + j * 256;
                int row = id >> 3, q = id & 7;
                CP16(sb + stg + row * 144 + q * 16, Au + (size_t)(bm + row) * K + k0 + q * 4);
            }
            #pragma unroll
            for (int j = 0; j < 4; j++) {
                int id = tid + j * 256;
                int row = id >> 3, q = id & 7;
                CP16(sb + stg + 9216 + row * 144 + q * 16, W + (size_t)(bn + row) * K + k0 + q * 4);
            }
            CP_COMMIT();
            CP_WAIT(1);
        } else {
            CP_WAIT(0);
        }
        __syncthreads();
        const float* tA = sf + (c & 1) * (GSTT / 4);
        const float* tB = tA + 2304;
        #pragma unroll
        for (int ks = 0; ks < 4; ks++) {
            const int ko = ks * 8;
            uint32_t af[2][4], bf[4][2];
            #pragma unroll
            for (int mt = 0; mt < 2; mt++) {
                int r0 = (wm * 32 + mt * 16 + lr) * 36 + ko + lc;
                af[mt][0] = __float_as_uint(tA[r0]);
                af[mt][1] = __float_as_uint(tA[r0 + 8 * 36]);
                af[mt][2] = __float_as_uint(tA[r0 + 4]);
                af[mt][3] = __float_as_uint(tA[r0 + 8 * 36 + 4]);
            }
            #pragma unroll
            for (int nt = 0; nt < 4; nt++) {
                int n0 = (wn * 32 + nt * 8 + lr) * 36 + ko + lc;
                bf[nt][0] = __float_as_uint(tB[n0]);
                bf[nt][1] = __float_as_uint(tB[n0 + 4]);
            }
            #pragma unroll
            for (int mt = 0; mt < 2; mt++)
                #pragma unroll
                for (int nt = 0; nt < 4; nt++)
                    MMA_TF32(acc[mt][nt], af[mt], bf[nt]);
        }
        __syncthreads();
    }

    // ---------------- epilogues ----------------
    if (mode == EP_SIMDOT) {
        float* simS = (float*)smem;
        if (tid < 64) simS[tid] = 0.f;
        __syncthreads();
        #pragma unroll
        for (int mt = 0; mt < 2; mt++) {
            int row0 = bm + wm * 32 + mt * 16 + lr;
            float d0 = 0.f, d1 = 0.f;
            #pragma unroll
            for (int nt = 0; nt < 4; nt++) {
                int col = bn + wn * 32 + nt * 8 + 2 * lc;
                float2 s0 = *(const float2*)(R + (size_t)row0 * 128 + col);
                float2 s1 = *(const float2*)(R + (size_t)(row0 + 8) * 128 + col);
                d0 += acc[mt][nt][0] * s0.x + acc[mt][nt][1] * s0.y;
                d1 += acc[mt][nt][2] * s1.x + acc[mt][nt][3] * s1.y;
            }
            d0 += __shfl_xor_sync(0xffffffffu, d0, 1);
            d0 += __shfl_xor_sync(0xffffffffu, d0, 2);
            d1 += __shfl_xor_sync(0xffffffffu, d1, 1);
            d1 += __shfl_xor_sync(0xffffffffu, d1, 2);
            if (lc == 0) {
                atomicAdd(&simS[wm * 32 + mt * 16 + lr], d0);
                atomicAdd(&simS[wm * 32 + mt * 16 + lr + 8], d1);
            }
        }
        __syncthreads();
        if (tid < 64) C[bm + tid] = simS[tid] * (1.f / 2048.f);
        return;
    }

    #pragma unroll
    for (int mt = 0; mt < 2; mt++) {
        int row = bm + wm * 32 + mt * 16 + lr;
        #pragma unroll
        for (int nt = 0; nt < 4; nt++) {
            int col = bn + wn * 32 + nt * 8 + 2 * lc;
            float2 b2 = *(const float2*)(bias + col);
            float* a = acc[mt][nt];
            a[0] += b2.x; a[1] += b2.y; a[2] += b2.x; a[3] += b2.y;
            if (mode == EP_LN || mode == EP_LN2) {
                float2 r0 = *(const float2*)(R + (size_t)row * ldc + col);
                float2 r1 = *(const float2*)(R + (size_t)(row + 8) * ldc + col);
                a[0] += r0.x; a[1] += r0.y; a[2] += r1.x; a[3] += r1.y;
            } else if (mode == EP_GELU) {
                a[0] = gelu_f(a[0]); a[1] = gelu_f(a[1]);
                a[2] = gelu_f(a[2]); a[3] = gelu_f(a[3]);
            } else if (mode == EP_FINAL) {
                float2 r0 = *(const float2*)(R + (size_t)row * ldc + col);
                float2 r1 = *(const float2*)(R + (size_t)(row + 8) * ldc + col);
                float sc0 = rs[row], sc1 = rs[row + 8];
                a[0] = r0.x + sc0 * a[0]; a[1] = r0.y + sc0 * a[1];
                a[2] = r1.x + sc1 * a[2]; a[3] = r1.y + sc1 * a[3];
            }
        }
    }

    if (mode == EP_LN || mode == EP_LN2 || mode == EP_COS) {
        float* ps = (float*)smem;        // [64][4]
        float* ps2 = ps + 256;
        #pragma unroll
        for (int mt = 0; mt < 2; mt++) {
            float p0 = 0.f, p1 = 0.f, q0 = 0.f, q1 = 0.f;
            #pragma unroll
            for (int nt = 0; nt < 4; nt++) {
                float* a = acc[mt][nt];
                p0 += a[0] + a[1]; q0 += a[0] * a[0] + a[1] * a[1];
                p1 += a[2] + a[3]; q1 += a[2] * a[2] + a[3] * a[3];
            }
            p0 += __shfl_xor_sync(0xffffffffu, p0, 1); p0 += __shfl_xor_sync(0xffffffffu, p0, 2);
            p1 += __shfl_xor_sync(0xffffffffu, p1, 1); p1 += __shfl_xor_sync(0xffffffffu, p1, 2);
            q0 += __shfl_xor_sync(0xffffffffu, q0, 1); q0 += __shfl_xor_sync(0xffffffffu, q0, 2);
            q1 += __shfl_xor_sync(0xffffffffu, q1, 1); q1 += __shfl_xor_sync(0xffffffffu, q1, 2);
            if (lc == 0) {
                int r0l = wm * 32 + mt * 16 + lr;
                ps[r0l * 4 + wn] = p0; ps2[r0l * 4 + wn] = q0;
                ps[(r0l + 8) * 4 + wn] = p1; ps2[(r0l + 8) * 4 + wn] = q1;
            }
        }
        __syncthreads();
        #pragma unroll
        for (int mt = 0; mt < 2; mt++) {
            int r0l = wm * 32 + mt * 16 + lr;
            float s0 = 0.f, t0 = 0.f, s1 = 0.f, t1 = 0.f;
            #pragma unroll
            for (int w4 = 0; w4 < 4; w4++) {
                s0 += ps[r0l * 4 + w4]; t0 += ps2[r0l * 4 + w4];
                s1 += ps[(r0l + 8) * 4 + w4]; t1 += ps2[(r0l + 8) * 4 + w4];
            }
            int row0 = bm + r0l;
            if (mode == EP_COS) {
                float i0 = 1.f / fmaxf(sqrtf(t0), 1e-8f);
                float i1 = 1.f / fmaxf(sqrtf(t1), 1e-8f);
                #pragma unroll
                for (int nt = 0; nt < 4; nt++) {
                    int col = bn + wn * 32 + nt * 8 + 2 * lc;
                    float* a = acc[mt][nt];
                    size_t i0x = (size_t)row0 * ldc + col, i1x = (size_t)(row0 + 8) * ldc + col;
                    *(float2*)(Ct + i0x) = make_float2(a[0], a[1]);   // raw embed
                    *(float2*)(Ct + i1x) = make_float2(a[2], a[3]);
                    *(float2*)(C + i0x) = make_float2(a[0] * i0, a[1] * i0);  // normalized
                    *(float2*)(C + i1x) = make_float2(a[2] * i1, a[3] * i1);
                }
            } else {
                float mu0 = s0 * (1.f / 128.f), mu1 = s1 * (1.f / 128.f);
                float rs0 = rsqrtf(t0 * (1.f / 128.f) - mu0 * mu0 + 1e-5f);
                float rs1 = rsqrtf(t1 * (1.f / 128.f) - mu1 * mu1 + 1e-5f);
                #pragma unroll
                for (int nt = 0; nt < 4; nt++) {
                    int col = bn + wn * 32 + nt * 8 + 2 * lc;
                    float* a = acc[mt][nt];
                    float2 g2 = *(const float2*)(gam + col);
                    float2 be2 = *(const float2*)(bet + col);
                    float w0 = (a[0] - mu0) * rs0 * g2.x + be2.x;
                    float w1 = (a[1] - mu0) * rs0 * g2.y + be2.y;
                    float w2 = (a[2] - mu1) * rs1 * g2.x + be2.x;
                    float w3 = (a[3] - mu1) * rs1 * g2.y + be2.y;
                    size_t i0x = (size_t)row0 * ldc + col, i1x = (size_t)(row0 + 8) * ldc + col;
                    *(float2*)(C + i0x) = make_float2(w0, w1);
                    *(float2*)(C + i1x) = make_float2(w2, w3);
                }
            }
        }
    } else {
        #pragma unroll
        for (int mt = 0; mt < 2; mt++) {
            int row = bm + wm * 32 + mt * 16 + lr;
            #pragma unroll
            for (int nt = 0; nt < 4; nt++) {
                int col = bn + wn * 32 + nt * 8 + 2 * lc;
                float* a = acc[mt][nt];
                size_t i0x = (size_t)row * ldc + col, i1x = (size_t)(row + 8) * ldc + col;
                *(float2*)(C + i0x) = make_float2(a[0], a[1]);
                *(float2*)(C + i1x) = make_float2(a[2], a[3]);
            }
        }
    }
}

// ============== M covariance: M[b] += sn^T tn (contract over s) ==============
// Tiles stored [s][d]: 32 rows x 132 floats (528B stride). A-side read transposed.
#define CSTT 33792
__global__ void __launch_bounds__(256, 2) mcov_tf(
    const float* __restrict__ sn, const float* __restrict__ tn, float* __restrict__ M)
{
    extern __shared__ char smem[];
    float* sf = (float*)smem;
    uint32_t sb = smem_to_u32(smem);
    const int tid = threadIdx.x, lane = tid & 31, wid = tid >> 5;
    const int wm = wid >> 2, wn = wid & 3;
    const int lr = lane >> 2, lc = lane & 3;
    const int b = blockIdx.y, split = blockIdx.x;
    const size_t srow0 = (size_t)b * SS + split * 128;

    float acc[4][4][4];
    #pragma unroll
    for (int i = 0; i < 4; i++)
        #pragma unroll
        for (int j = 0; j < 4; j++)
            #pragma unroll
            for (int k = 0; k < 4; k++) acc[i][j][k] = 0.f;

    #pragma unroll
    for (int j = 0; j < 4; j++) {
        int id = tid + j * 256;
        int row = id >> 5, q = id & 31;
        CP16(sb + row * 528 + q * 16, sn + (srow0 + row) * 128 + q * 4);
        CP16(sb + 16896 + row * 528 + q * 16, tn + (srow0 + row) * 128 + q * 4);
    }
    CP_COMMIT();

    for (int c = 0; c < 4; c++) {
        if (c + 1 < 4) {
            uint32_t stg = ((c + 1) & 1) * CSTT;
            const size_t so = srow0 + (size_t)(c + 1) * 32;
            #pragma unroll
            for (int j = 0; j < 4; j++) {
                int id = tid + j * 256;
                int row = id >> 5, q = id & 31;
                CP16(sb + stg + row * 528 + q * 16, sn + (so + row) * 128 + q * 4);
                CP16(sb + stg + 16896 + row * 528 + q * 16, tn + (so + row) * 128 + q * 4);
            }
            CP_COMMIT();
            CP_WAIT(1);
        } else {
            CP_WAIT(0);
        }
        __syncthreads();
        const float* tS = sf + (c & 1) * (CSTT / 4);
        const float* tT = tS + 4224;
        #pragma unroll
        for (int ks = 0; ks < 4; ks++) {
            const int ko = ks * 8;
            uint32_t af[4][4], bf[4][2];
            #pragma unroll
            for (int mt = 0; mt < 4; mt++) {
                int d0 = wm * 64 + mt * 16 + lr;
                af[mt][0] = __float_as_uint(tS[(ko + lc) * 132 + d0]);
                af[mt][1] = __float_as_uint(tS[(ko + lc) * 132 + d0 + 8]);
                af[mt][2] = __float_as_uint(tS[(ko + lc + 4) * 132 + d0]);
                af[mt][3] = __float_as_uint(tS[(ko + lc + 4) * 132 + d0 + 8]);
            }
            #pragma unroll
            for (int nt = 0; nt < 4; nt++) {
                int e0 = wn * 32 + nt * 8 + lr;
                bf[nt][0] = __float_as_uint(tT[(ko + lc) * 132 + e0]);
                bf[nt][1] = __float_as_uint(tT[(ko + lc + 4) * 132 + e0]);
            }
            #pragma unroll
            for (int mt = 0; mt < 4; mt++)
                #pragma unroll
                for (int nt = 0; nt < 4; nt++)
                    MMA_TF32(acc[mt][nt], af[mt], bf[nt]);
        }
        __syncthreads();
    }

    float* Mb = M + (size_t)b * 16384;
    #pragma unroll
    for (int mt = 0; mt < 4; mt++) {
        int row = wm * 64 + mt * 16 + lr;
        #pragma unroll
        for (int nt = 0; nt < 4; nt++) {
            int col = wn * 32 + nt * 8 + 2 * lc;
            atomicAdd(&Mb[(size_t)row * 128 + col], acc[mt][nt][0]);
            atomicAdd(&Mb[(size_t)row * 128 + col + 1], acc[mt][nt][1]);
            atomicAdd(&Mb[(size_t)(row + 8) * 128 + col], acc[mt][nt][2]);
            atomicAdd(&Mb[(size_t)(row + 8) * 128 + col + 1], acc[mt][nt][3]);
        }
    }
}

// ---------------- local windowed causal attention ----------------
__global__ __launch_bounds__(64) void lw_attn_k(const float* __restrict__ qkv,
                                                float* __restrict__ outp)
{
    int g = blockIdx.x, h = blockIdx.y, i = threadIdx.x;
    __shared__ float ks[64][17];
    __shared__ float vs[64][17];
    size_t tbase = (size_t)g * 64;
    const float* kp = qkv + (tbase + i) * 384 + 128 + h * 16;
    const float* vp = kp + 128;
    #pragma unroll
    for (int d = 0; d < 16; d++) { ks[i][d] = kp[d]; vs[i][d] = vp[d]; }
    float q[16];
    const float* qp = qkv + (tbase + i) * 384 + h * 16;
    #pragma unroll
    for (int d = 0; d < 16; d++) q[d] = qp[d];
    __syncthreads();
    float sc[64];
    float mx = -1e30f;
    #pragma unroll
    for (int j = 0; j < 64; j++) {
        float dv = 0.f;
        #pragma unroll
        for (int d = 0; d < 16; d++) dv += q[d] * ks[j][d];
        sc[j] = (j <= i) ? dv * 0.25f : -INFINITY;
        mx = fmaxf(mx, sc[j]);
    }
    float sum = 0.f;
    #pragma unroll
    for (int j = 0; j < 64; j++) { float e = expf(sc[j] - mx); sc[j] = e; sum += e; }
    float o[16] = {};
    #pragma unroll
    for (int j = 0; j < 64; j++) {
        float w = sc[j];
        #pragma unroll
        for (int d = 0; d < 16; d++) o[d] += w * vs[j][d];
    }
    float inv = 1.f / sum;
    float* op = outp + (tbase + i) * 128 + h * 16;
    #pragma unroll
    for (int d = 0; d < 16; d++) op[d] = o[d] * inv;
}

// ---------------- interaction MHA (len = B = 8) ----------------
__global__ __launch_bounds__(64) void int_attn_k(const float* __restrict__ qkv,
                                                 float* __restrict__ outp)
{
    int s = blockIdx.x, tid = threadIdx.x;
    __shared__ float kvs[8][256];
    for (int idx = tid; idx < 8 * 256; idx += 64) {
        int jb = idx >> 8, c = idx & 255;
        kvs[jb][c] = qkv[((size_t)jb * SS + s) * 384 + 128 + c];
    }
    __syncthreads();
    int h = tid >> 3, qb = tid & 7;
    float q[16];
    const float* qp = qkv + ((size_t)qb * SS + s) * 384 + h * 16;
    #pragma unroll
    for (int d = 0; d < 16; d++) q[d] = qp[d];
    float sc[8];
    float mx = -1e30f;
    #pragma unroll
    for (int jb = 0; jb < 8; jb++) {
        float dv = 0.f;
        #pragma unroll
        for (int d = 0; d < 16; d++) dv += q[d] * kvs[jb][h * 16 + d];
        sc[jb] = dv * 0.25f;
        mx = fmaxf(mx, sc[jb]);
    }
    float sum = 0.f;
    #pragma unroll
    for (int jb = 0; jb < 8; jb++) { float e = expf(sc[jb] - mx); sc[jb] = e; sum += e; }
    float o[16] = {};
    #pragma unroll
    for (int jb = 0; jb < 8; jb++) {
        float w = sc[jb];
        #pragma unroll
        for (int d = 0; d < 16; d++) o[d] += w * kvs[jb][128 + h * 16 + d];
    }
    float inv = 1.f / sum;
    float* op = outp + ((size_t)qb * SS + s) * 384 + h * 16;  // unused layout guard
    (void)op;
    float* op2 = outp + ((size_t)qb * SS + s) * 128 + h * 16;
    #pragma unroll
    for (int d = 0; d < 16; d++) op2[d] = o[d] * inv;
}

extern "C" void kernel_launch(void* const* d_in, const int* in_sizes, int n_in,
                              void* d_out, int out_size)
{
    const float* x        = (const float*)d_in[0];
    const float* sp       = (const float*)d_in[1];
    const float* tp       = (const float*)d_in[2];
    const float* lw_in_w  = (const float*)d_in[3];
    const float* lw_in_b  = (const float*)d_in[4];
    const float* lw_out_w = (const float*)d_in[5];
    const float* lw_out_b = (const float*)d_in[6];
    const float* spat_w   = (const float*)d_in[7];
    const float* spat_b   = (const float*)d_in[8];
    const float* temp_w   = (const float*)d_in[9];
    const float* temp_b   = (const float*)d_in[10];
    const float* int_in_w = (const float*)d_in[11];
    const float* int_in_b = (const float*)d_in[12];
    const float* int_out_w= (const float*)d_in[13];
    const float* int_out_b= (const float*)d_in[14];
    const float* ffn_w1   = (const float*)d_in[15];
    const float* ffn_b1   = (const float*)d_in[16];
    const float* ffn_w2   = (const float*)d_in[17];
    const float* ffn_b2   = (const float*)d_in[18];
    const float* ln1_g    = (const float*)d_in[19];
    const float* ln1_b    = (const float*)d_in[20];
    const float* ln2_g    = (const float*)d_in[21];
    const float* ln2_b    = (const float*)d_in[22];
    float* out = (float*)d_out;

    float* f32 = nullptr;
    cudaGetSymbolAddress((void**)&f32, g_f32);

    static cudaStream_t s2 = nullptr;
    static cudaEvent_t evF = nullptr, evJ = nullptr;
    static bool init_done = false;
    if (!init_done) {
        cudaFuncSetAttribute(gemm_tf, cudaFuncAttributeMaxDynamicSharedMemorySize, 2 * GSTT);
        cudaFuncSetAttribute(mcov_tf, cudaFuncAttributeMaxDynamicSharedMemorySize, 2 * CSTT);
        cudaStreamCreateWithFlags(&s2, cudaStreamNonBlocking);
        cudaEventCreateWithFlags(&evF, cudaEventDisableTiming);
        cudaEventCreateWithFlags(&evJ, cudaEventDisableTiming);
        init_done = true;
    }

    float* qkv   = f32 + F_QKV;
    float* qkv2  = f32 + F_QKV2;
    float* att   = f32 + F_ATT;
    float* att2  = f32 + F_ATT2;
    float* bufb  = f32 + F_BUFB;
    float* bufh  = f32 + F_BUFH;
    float* bufc  = f32 + F_BUFC;
    float* se    = f32 + F_SE;
    float* sn    = f32 + F_SN;
    float* te    = f32 + F_TE;
    float* tn    = f32 + F_TN;
    float* bM    = f32 + F_M;
    float* bsim  = f32 + F_SIM;

    // ---- fork ----
    cudaEventRecord(evF, 0);
    cudaStreamWaitEvent(s2, evF, 0);

    // ===== main stream: x-chain =====
    gemm_tf<<<dim3(3, 256), 256, 2 * GSTT>>>(
        x, nullptr, lw_in_w, lw_in_b, qkv, nullptr,
        nullptr, nullptr, nullptr, nullptr, 128, 384, EP_F32, 0);
    lw_attn_k<<<dim3(256, 8), 64>>>(qkv, att);
    gemm_tf<<<dim3(1, 256), 256, 2 * GSTT>>>(
        att, nullptr, lw_out_w, lw_out_b, bufb, nullptr,
        x, nullptr, ln1_g, ln1_b, 128, 128, EP_LN, 0);
    gemm_tf<<<dim3(4, 256), 256, 2 * GSTT>>>(
        bufb, nullptr, ffn_w1, ffn_b1, bufh, nullptr,
        nullptr, nullptr, nullptr, nullptr, 128, 512, EP_GELU, 0);
    gemm_tf<<<dim3(1, 256), 256, 2 * GSTT>>>(
        bufh, nullptr, ffn_w2, ffn_b2, bufc, nullptr,
        bufb, nullptr, ln2_g, ln2_b, 512, 128, EP_LN2, 0);

    // ===== stream 2: spatio-temporal chain =====
    zero_k<<<512, 256, 0, s2>>>(bM, 8 * 128 * 128);
    gemm_tf<<<dim3(1, 256), 256, 2 * GSTT, s2>>>(
        sp, nullptr, spat_w, spat_b, sn, se,
        nullptr, nullptr, nullptr, nullptr, 128, 128, EP_COS, 0);
    gemm_tf<<<dim3(1, 256), 256, 2 * GSTT, s2>>>(
        tp, nullptr, temp_w, temp_b, tn, te,
        nullptr, nullptr, nullptr, nullptr, 128, 128, EP_COS, 0);
    mcov_tf<<<dim3(16, 8), 256, 2 * CSTT, s2>>>(sn, tn, bM);
    gemm_tf<<<dim3(1, 256), 256, 2 * GSTT, s2>>>(
        tn, nullptr, bM, nullptr, bsim, nullptr,
        sn, nullptr, nullptr, nullptr, 128, 0, EP_SIMDOT, 16384);
    gemm_tf<<<dim3(3, 256), 256, 2 * GSTT, s2>>>(
        se, te, int_in_w, int_in_b, qkv2, nullptr,
        nullptr, nullptr, nullptr, nullptr, 128, 384, EP_F32, 0);
    int_attn_k<<<SS, 64, 0, s2>>>(qkv2, att2);
    cudaEventRecord(evJ, s2);

    // ---- join + final ----
    cudaStreamWaitEvent(0, evJ, 0);
    gemm_tf<<<dim3(1, 256), 256, 2 * GSTT>>>(
        att2, nullptr, int_out_w, int_out_b, out, nullptr,
        bufc, bsim, nullptr, nullptr, 128, 128, EP_FINAL, 0);
}

// round 12
// speedup vs baseline: 1.5143x; 1.0070x over previous
#include <cuda_runtime.h>
#include <cstdint>
#include <math.h>

#define BB 8
#define SS 2048
#define TT 16384

// ---------------- fp32 scratch ----------------
#define F_QKV  0u            // 16384*384
#define F_QKV2 6291456u      // 16384*384
#define F_ATT  12582912u     // 16384*128
#define F_ATT2 14680064u
#define F_BUFB 16777216u
#define F_BUFH 18874368u     // 16384*512
#define F_BUFC 27262976u
#define F_SE   29360128u
#define F_SN   31457280u
#define F_TE   33554432u
#define F_TN   35651584u
#define F_M    37748736u     // 8*128*128
#define F_SIM  37879808u     // 16384
#define F_TOT  37896192u
__device__ float g_f32[F_TOT];

enum { EP_F32 = 0, EP_LN = 1, EP_GELU = 2, EP_LN2 = 3, EP_COS = 4, EP_FINAL = 5, EP_SIMDOT = 6 };

__device__ __forceinline__ uint32_t smem_to_u32(const void* p) {
    uint32_t a;
    asm("{ .reg .u64 t; cvta.to.shared.u64 t, %1; cvt.u32.u64 %0, t; }" : "=r"(a) : "l"(p));
    return a;
}

#define CP16(dst, src) do { \
    unsigned long long _gs = (unsigned long long)__cvta_generic_to_global((const void*)(src)); \
    asm volatile("cp.async.cg.shared.global [%0], [%1], 16;" :: "r"(dst), "l"(_gs)); } while (0)
#define CP_COMMIT() asm volatile("cp.async.commit_group;" ::: "memory")
#define CP_WAIT(n) asm volatile("cp.async.wait_group %0;" :: "n"(n) : "memory")

// tf32 mma: D(16x8) += A(16x8) * B(8x8); raw f32 regs truncated to tf32 by HW
#define MMA_TF32(c, a, b) \
    asm volatile("mma.sync.aligned.m16n8k8.row.col.f32.tf32.tf32.f32 " \
        "{%0,%1,%2,%3}, {%4,%5,%6,%7}, {%8,%9}, {%0,%1,%2,%3};" \
        : "+f"((c)[0]), "+f"((c)[1]), "+f"((c)[2]), "+f"((c)[3]) \
        : "r"((a)[0]), "r"((a)[1]), "r"((a)[2]), "r"((a)[3]), "r"((b)[0]), "r"((b)[1]))

__device__ __forceinline__ float gelu_f(float v) {
    return 0.5f * v * (1.0f + erff(v * 0.70710678118654752f));
}

__global__ void zero_k(float* p, int n)
{
    int i = blockIdx.x * 256 + threadIdx.x;
    if (i < n) p[i] = 0.f;
}

// ============== generic tf32 GEMM: C[M,N] = A @ W^T ==============
// Tile 64(M) x 128(N), 256 threads = 8 warps (2 wm x 4 wn), warp tile 32x32.
// smem stage (27648B): A +0 (64 rows x 36 floats), B +9216 (128 rows x 36 floats).
// Single-sync double-buffered pipeline. Optional dual-problem mode (dualY>0).
#define GSTT 27648
__global__ void __launch_bounds__(256, 3) gemm_tf(
    const float* __restrict__ A, const float* __restrict__ A2,
    const float* __restrict__ W,
    const float* __restrict__ bias, float* __restrict__ C,
    float* __restrict__ Ct,
    const float* __restrict__ Wd, const float* __restrict__ biasd,
    float* __restrict__ Cd, float* __restrict__ Ctd,
    const float* __restrict__ R, const float* __restrict__ rs,
    const float* __restrict__ gam, const float* __restrict__ bet,
    int K, int ldc, int mode, int batchW, int dualY)
{
    extern __shared__ char smem[];
    float* sf = (float*)smem;
    uint32_t sb = smem_to_u32(smem);
    const int tid = threadIdx.x, lane = tid & 31, wid = tid >> 5;
    const int wm = wid >> 2, wn = wid & 3;
    const int lr = lane >> 2, lc = lane & 3;
    int by = blockIdx.y;
    const int bn = blockIdx.x * 128;

    const float* Au = A;
    if (dualY > 0 && by >= dualY) {
        by -= dualY;
        Au = A2; W = Wd; bias = biasd; C = Cd; Ct = Ctd;
    } else if (dualY == 0 && A2 && bn > 0) {
        Au = A2;
    }
    const int bm = by * 64;
    if (batchW) W += (size_t)(bm >> 11) * (size_t)batchW;

    const int nch = K >> 5;

    float acc[2][4][4];
    #pragma unroll
    for (int i = 0; i < 2; i++)
        #pragma unroll
        for (int j = 0; j < 4; j++)
            #pragma unroll
            for (int k = 0; k < 4; k++) acc[i][j][k] = 0.f;

    // loader indices
    const int rowA = tid >> 3, qA = tid & 7;              // +256: rowA+32
    // prologue: chunk 0 -> stage 0
    #pragma unroll
    for (int j = 0; j < 2; j++) {
        int row = rowA + j * 32;
        CP16(sb + row * 144 + qA * 16, Au + (size_t)(bm + row) * K + qA * 4);
    }
    #pragma unroll
    for (int j = 0; j < 4; j++) {
        int row = rowA + j * 32;
        CP16(sb + 9216 + row * 144 + qA * 16, W + (size_t)(bn + row) * K + qA * 4);
    }
    CP_COMMIT();

    for (int c = 0; c < nch; c++) {
        CP_WAIT(0);
        __syncthreads();
        if (c + 1 < nch) {
            uint32_t stg = ((c + 1) & 1) * GSTT;
            const int k0 = (c + 1) * 32;
            #pragma unroll
            for (int j = 0; j < 2; j++) {
                int row = rowA + j * 32;
                CP16(sb + stg + row * 144 + qA * 16, Au + (size_t)(bm + row) * K + k0 + qA * 4);
            }
            #pragma unroll
            for (int j = 0; j < 4; j++) {
                int row = rowA + j * 32;
                CP16(sb + stg + 9216 + row * 144 + qA * 16, W + (size_t)(bn + row) * K + k0 + qA * 4);
            }
            CP_COMMIT();
        }
        const float* tA = sf + (c & 1) * (GSTT / 4);
        const float* tB = tA + 2304;
        #pragma unroll
        for (int ks = 0; ks < 4; ks++) {
            const int ko = ks * 8;
            uint32_t af[2][4], bf[4][2];
            #pragma unroll
            for (int mt = 0; mt < 2; mt++) {
                int r0 = (wm * 32 + mt * 16 + lr) * 36 + ko + lc;
                af[mt][0] = __float_as_uint(tA[r0]);
                af[mt][1] = __float_as_uint(tA[r0 + 8 * 36]);
                af[mt][2] = __float_as_uint(tA[r0 + 4]);
                af[mt][3] = __float_as_uint(tA[r0 + 8 * 36 + 4]);
            }
            #pragma unroll
            for (int nt = 0; nt < 4; nt++) {
                int n0 = (wn * 32 + nt * 8 + lr) * 36 + ko + lc;
                bf[nt][0] = __float_as_uint(tB[n0]);
                bf[nt][1] = __float_as_uint(tB[n0 + 4]);
            }
            #pragma unroll
            for (int mt = 0; mt < 2; mt++)
                #pragma unroll
                for (int nt = 0; nt < 4; nt++)
                    MMA_TF32(acc[mt][nt], af[mt], bf[nt]);
        }
    }
    __syncthreads();

    // ---------------- epilogues ----------------
    if (mode == EP_SIMDOT) {
        float* simS = (float*)smem;
        if (tid < 64) simS[tid] = 0.f;
        __syncthreads();
        #pragma unroll
        for (int mt = 0; mt < 2; mt++) {
            int row0 = bm + wm * 32 + mt * 16 + lr;
            float d0 = 0.f, d1 = 0.f;
            #pragma unroll
            for (int nt = 0; nt < 4; nt++) {
                int col = bn + wn * 32 + nt * 8 + 2 * lc;
                float2 s0 = *(const float2*)(R + (size_t)row0 * 128 + col);
                float2 s1 = *(const float2*)(R + (size_t)(row0 + 8) * 128 + col);
                d0 += acc[mt][nt][0] * s0.x + acc[mt][nt][1] * s0.y;
                d1 += acc[mt][nt][2] * s1.x + acc[mt][nt][3] * s1.y;
            }
            d0 += __shfl_xor_sync(0xffffffffu, d0, 1);
            d0 += __shfl_xor_sync(0xffffffffu, d0, 2);
            d1 += __shfl_xor_sync(0xffffffffu, d1, 1);
            d1 += __shfl_xor_sync(0xffffffffu, d1, 2);
            if (lc == 0) {
                atomicAdd(&simS[wm * 32 + mt * 16 + lr], d0);
                atomicAdd(&simS[wm * 32 + mt * 16 + lr + 8], d1);
            }
        }
        __syncthreads();
        if (tid < 64) C[bm + tid] = simS[tid] * (1.f / 2048.f);
        return;
    }

    #pragma unroll
    for (int mt = 0; mt < 2; mt++) {
        int row = bm + wm * 32 + mt * 16 + lr;
        #pragma unroll
        for (int nt = 0; nt < 4; nt++) {
            int col = bn + wn * 32 + nt * 8 + 2 * lc;
            float2 b2 = *(const float2*)(bias + col);
            float* a = acc[mt][nt];
            a[0] += b2.x; a[1] += b2.y; a[2] += b2.x; a[3] += b2.y;
            if (mode == EP_LN || mode == EP_LN2) {
                float2 r0 = *(const float2*)(R + (size_t)row * ldc + col);
                float2 r1 = *(const float2*)(R + (size_t)(row + 8) * ldc + col);
                a[0] += r0.x; a[1] += r0.y; a[2] += r1.x; a[3] += r1.y;
            } else if (mode == EP_GELU) {
                a[0] = gelu_f(a[0]); a[1] = gelu_f(a[1]);
                a[2] = gelu_f(a[2]); a[3] = gelu_f(a[3]);
            } else if (mode == EP_FINAL) {
                float2 r0 = *(const float2*)(R + (size_t)row * ldc + col);
                float2 r1 = *(const float2*)(R + (size_t)(row + 8) * ldc + col);
                float sc0 = rs[row], sc1 = rs[row + 8];
                a[0] = r0.x + sc0 * a[0]; a[1] = r0.y + sc0 * a[1];
                a[2] = r1.x + sc1 * a[2]; a[3] = r1.y + sc1 * a[3];
            }
        }
    }

    if (mode == EP_LN || mode == EP_LN2 || mode == EP_COS) {
        float* ps = (float*)smem;        // [64][4]
        float* ps2 = ps + 256;
        #pragma unroll
        for (int mt = 0; mt < 2; mt++) {
            float p0 = 0.f, p1 = 0.f, q0 = 0.f, q1 = 0.f;
            #pragma unroll
            for (int nt = 0; nt < 4; nt++) {
                float* a = acc[mt][nt];
                p0 += a[0] + a[1]; q0 += a[0] * a[0] + a[1] * a[1];
                p1 += a[2] + a[3]; q1 += a[2] * a[2] + a[3] * a[3];
            }
            p0 += __shfl_xor_sync(0xffffffffu, p0, 1); p0 += __shfl_xor_sync(0xffffffffu, p0, 2);
            p1 += __shfl_xor_sync(0xffffffffu, p1, 1); p1 += __shfl_xor_sync(0xffffffffu, p1, 2);
            q0 += __shfl_xor_sync(0xffffffffu, q0, 1); q0 += __shfl_xor_sync(0xffffffffu, q0, 2);
            q1 += __shfl_xor_sync(0xffffffffu, q1, 1); q1 += __shfl_xor_sync(0xffffffffu, q1, 2);
            if (lc == 0) {
                int r0l = wm * 32 + mt * 16 + lr;
                ps[r0l * 4 + wn] = p0; ps2[r0l * 4 + wn] = q0;
                ps[(r0l + 8) * 4 + wn] = p1; ps2[(r0l + 8) * 4 + wn] = q1;
            }
        }
        __syncthreads();
        #pragma unroll
        for (int mt = 0; mt < 2; mt++) {
            int r0l = wm * 32 + mt * 16 + lr;
            float s0 = 0.f, t0 = 0.f, s1 = 0.f, t1 = 0.f;
            #pragma unroll
            for (int w4 = 0; w4 < 4; w4++) {
                s0 += ps[r0l * 4 + w4]; t0 += ps2[r0l * 4 + w4];
                s1 += ps[(r0l + 8) * 4 + w4]; t1 += ps2[(r0l + 8) * 4 + w4];
            }
            int row0 = bm + r0l;
            if (mode == EP_COS) {
                float i0 = 1.f / fmaxf(sqrtf(t0), 1e-8f);
                float i1 = 1.f / fmaxf(sqrtf(t1), 1e-8f);
                #pragma unroll
                for (int nt = 0; nt < 4; nt++) {
                    int col = bn + wn * 32 + nt * 8 + 2 * lc;
                    float* a = acc[mt][nt];
                    size_t i0x = (size_t)row0 * ldc + col, i1x = (size_t)(row0 + 8) * ldc + col;
                    *(float2*)(Ct + i0x) = make_float2(a[0], a[1]);   // raw embed
                    *(float2*)(Ct + i1x) = make_float2(a[2], a[3]);
                    *(float2*)(C + i0x) = make_float2(a[0] * i0, a[1] * i0);  // normalized
                    *(float2*)(C + i1x) = make_float2(a[2] * i1, a[3] * i1);
                }
            } else {
                float mu0 = s0 * (1.f / 128.f), mu1 = s1 * (1.f / 128.f);
                float rs0 = rsqrtf(t0 * (1.f / 128.f) - mu0 * mu0 + 1e-5f);
                float rs1 = rsqrtf(t1 * (1.f / 128.f) - mu1 * mu1 + 1e-5f);
                #pragma unroll
                for (int nt = 0; nt < 4; nt++) {
                    int col = bn + wn * 32 + nt * 8 + 2 * lc;
                    float* a = acc[mt][nt];
                    float2 g2 = *(const float2*)(gam + col);
                    float2 be2 = *(const float2*)(bet + col);
                    float w0 = (a[0] - mu0) * rs0 * g2.x + be2.x;
                    float w1 = (a[1] - mu0) * rs0 * g2.y + be2.y;
                    float w2 = (a[2] - mu1) * rs1 * g2.x + be2.x;
                    float w3 = (a[3] - mu1) * rs1 * g2.y + be2.y;
                    size_t i0x = (size_t)row0 * ldc + col, i1x = (size_t)(row0 + 8) * ldc + col;
                    *(float2*)(C + i0x) = make_float2(w0, w1);
                    *(float2*)(C + i1x) = make_float2(w2, w3);
                }
            }
        }
    } else {
        #pragma unroll
        for (int mt = 0; mt < 2; mt++) {
            int row = bm + wm * 32 + mt * 16 + lr;
            #pragma unroll
            for (int nt = 0; nt < 4; nt++) {
                int col = bn + wn * 32 + nt * 8 + 2 * lc;
                float* a = acc[mt][nt];
                size_t i0x = (size_t)row * ldc + col, i1x = (size_t)(row + 8) * ldc + col;
                *(float2*)(C + i0x) = make_float2(a[0], a[1]);
                *(float2*)(C + i1x) = make_float2(a[2], a[3]);
            }
        }
    }
}

// ============== M covariance: M[b] += sn^T tn (contract over s) ==============
// Tiles stored [s][d]: 32 rows x 132 floats (528B stride). A-side read transposed.
#define CSTT 33792
__global__ void __launch_bounds__(256, 2) mcov_tf(
    const float* __restrict__ sn, const float* __restrict__ tn, float* __restrict__ M)
{
    extern __shared__ char smem[];
    float* sf = (float*)smem;
    uint32_t sb = smem_to_u32(smem);
    const int tid = threadIdx.x, lane = tid & 31, wid = tid >> 5;
    const int wm = wid >> 2, wn = wid & 3;
    const int lr = lane >> 2, lc = lane & 3;
    const int b = blockIdx.y, split = blockIdx.x;
    const size_t srow0 = (size_t)b * SS + split * 128;

    float acc[4][4][4];
    #pragma unroll
    for (int i = 0; i < 4; i++)
        #pragma unroll
        for (int j = 0; j < 4; j++)
            #pragma unroll
            for (int k = 0; k < 4; k++) acc[i][j][k] = 0.f;

    const int rowL = tid >> 5, qL = tid & 31;   // 8 rows per pass, 4 passes
    #pragma unroll
    for (int j = 0; j < 4; j++) {
        int row = rowL + j * 8;
        CP16(sb + row * 528 + qL * 16, sn + (srow0 + row) * 128 + qL * 4);
        CP16(sb + 16896 + row * 528 + qL * 16, tn + (srow0 + row) * 128 + qL * 4);
    }
    CP_COMMIT();

    for (int c = 0; c < 4; c++) {
        CP_WAIT(0);
        __syncthreads();
        if (c + 1 < 4) {
            uint32_t stg = ((c + 1) & 1) * CSTT;
            const size_t so = srow0 + (size_t)(c + 1) * 32;
            #pragma unroll
            for (int j = 0; j < 4; j++) {
                int row = rowL + j * 8;
                CP16(sb + stg + row * 528 + qL * 16, sn + (so + row) * 128 + qL * 4);
                CP16(sb + stg + 16896 + row * 528 + qL * 16, tn + (so + row) * 128 + qL * 4);
            }
            CP_COMMIT();
        }
        const float* tS = sf + (c & 1) * (CSTT / 4);
        const float* tT = tS + 4224;
        #pragma unroll
        for (int ks = 0; ks < 4; ks++) {
            const int ko = ks * 8;
            uint32_t af[4][4], bf[4][2];
            #pragma unroll
            for (int mt = 0; mt < 4; mt++) {
                int d0 = wm * 64 + mt * 16 + lr;
                af[mt][0] = __float_as_uint(tS[(ko + lc) * 132 + d0]);
                af[mt][1] = __float_as_uint(tS[(ko + lc) * 132 + d0 + 8]);
                af[mt][2] = __float_as_uint(tS[(ko + lc + 4) * 132 + d0]);
                af[mt][3] = __float_as_uint(tS[(ko + lc + 4) * 132 + d0 + 8]);
            }
            #pragma unroll
            for (int nt = 0; nt < 4; nt++) {
                int e0 = wn * 32 + nt * 8 + lr;
                bf[nt][0] = __float_as_uint(tT[(ko + lc) * 132 + e0]);
                bf[nt][1] = __float_as_uint(tT[(ko + lc + 4) * 132 + e0]);
            }
            #pragma unroll
            for (int mt = 0; mt < 4; mt++)
                #pragma unroll
                for (int nt = 0; nt < 4; nt++)
                    MMA_TF32(acc[mt][nt], af[mt], bf[nt]);
        }
    }

    float* Mb = M + (size_t)b * 16384;
    #pragma unroll
    for (int mt = 0; mt < 4; mt++) {
        int row = wm * 64 + mt * 16 + lr;
        #pragma unroll
        for (int nt = 0; nt < 4; nt++) {
            int col = wn * 32 + nt * 8 + 2 * lc;
            atomicAdd(&Mb[(size_t)row * 128 + col], acc[mt][nt][0]);
            atomicAdd(&Mb[(size_t)row * 128 + col + 1], acc[mt][nt][1]);
            atomicAdd(&Mb[(size_t)(row + 8) * 128 + col], acc[mt][nt][2]);
            atomicAdd(&Mb[(size_t)(row + 8) * 128 + col + 1], acc[mt][nt][3]);
        }
    }
}

// ---------------- local windowed causal attention ----------------
__global__ __launch_bounds__(64) void lw_attn_k(const float* __restrict__ qkv,
                                                float* __restrict__ outp)
{
    int g = blockIdx.x, h = blockIdx.y, i = threadIdx.x;
    __shared__ float ks[64][17];
    __shared__ float vs[64][17];
    size_t tbase = (size_t)g * 64;
    const float* kp = qkv + (tbase + i) * 384 + 128 + h * 16;
    const float* vp = kp + 128;
    #pragma unroll
    for (int d = 0; d < 16; d++) { ks[i][d] = kp[d]; vs[i][d] = vp[d]; }
    float q[16];
    const float* qp = qkv + (tbase + i) * 384 + h * 16;
    #pragma unroll
    for (int d = 0; d < 16; d++) q[d] = qp[d];
    __syncthreads();
    float sc[64];
    float mx = -1e30f;
    #pragma unroll
    for (int j = 0; j < 64; j++) {
        float dv = 0.f;
        #pragma unroll
        for (int d = 0; d < 16; d++) dv += q[d] * ks[j][d];
        sc[j] = (j <= i) ? dv * 0.25f : -INFINITY;
        mx = fmaxf(mx, sc[j]);
    }
    float sum = 0.f;
    #pragma unroll
    for (int j = 0; j < 64; j++) { float e = expf(sc[j] - mx); sc[j] = e; sum += e; }
    float o[16] = {};
    #pragma unroll
    for (int j = 0; j < 64; j++) {
        float w = sc[j];
        #pragma unroll
        for (int d = 0; d < 16; d++) o[d] += w * vs[j][d];
    }
    float inv = 1.f / sum;
    float* op = outp + (tbase + i) * 128 + h * 16;
    #pragma unroll
    for (int d = 0; d < 16; d++) op[d] = o[d] * inv;
}

// ---------------- interaction MHA (len = B = 8) ----------------
__global__ __launch_bounds__(64) void int_attn_k(const float* __restrict__ qkv,
                                                 float* __restrict__ outp)
{
    int s = blockIdx.x, tid = threadIdx.x;
    __shared__ float kvs[8][256];
    for (int idx = tid; idx < 8 * 256; idx += 64) {
        int jb = idx >> 8, c = idx & 255;
        kvs[jb][c] = qkv[((size_t)jb * SS + s) * 384 + 128 + c];
    }
    __syncthreads();
    int h = tid >> 3, qb = tid & 7;
    float q[16];
    const float* qp = qkv + ((size_t)qb * SS + s) * 384 + h * 16;
    #pragma unroll
    for (int d = 0; d < 16; d++) q[d] = qp[d];
    float sc[8];
    float mx = -1e30f;
    #pragma unroll
    for (int jb = 0; jb < 8; jb++) {
        float dv = 0.f;
        #pragma unroll
        for (int d = 0; d < 16; d++) dv += q[d] * kvs[jb][h * 16 + d];
        sc[jb] = dv * 0.25f;
        mx = fmaxf(mx, sc[jb]);
    }
    float sum = 0.f;
    #pragma unroll
    for (int jb = 0; jb < 8; jb++) { float e = expf(sc[jb] - mx); sc[jb] = e; sum += e; }
    float o[16] = {};
    #pragma unroll
    for (int jb = 0; jb < 8; jb++) {
        float w = sc[jb];
        #pragma unroll
        for (int d = 0; d < 16; d++) o[d] += w * kvs[jb][128 + h * 16 + d];
    }
    float inv = 1.f / sum;
    float* op = outp + ((size_t)qb * SS + s) * 128 + h * 16;
    #pragma unroll
    for (int d = 0; d < 16; d++) op[d] = o[d] * inv;
}

extern "C" void kernel_launch(void* const* d_in, const int* in_sizes, int n_in,
                              void* d_out, int out_size)
{
    const float* x        = (const float*)d_in[0];
    const float* sp       = (const float*)d_in[1];
    const float* tp       = (const float*)d_in[2];
    const float* lw_in_w  = (const float*)d_in[3];
    const float* lw_in_b  = (const float*)d_in[4];
    const float* lw_out_w = (const float*)d_in[5];
    const float* lw_out_b = (const float*)d_in[6];
    const float* spat_w   = (const float*)d_in[7];
    const float* spat_b   = (const float*)d_in[8];
    const float* temp_w   = (const float*)d_in[9];
    const float* temp_b   = (const float*)d_in[10];
    const float* int_in_w = (const float*)d_in[11];
    const float* int_in_b = (const float*)d_in[12];
    const float* int_out_w= (const float*)d_in[13];
    const float* int_out_b= (const float*)d_in[14];
    const float* ffn_w1   = (const float*)d_in[15];
    const float* ffn_b1   = (const float*)d_in[16];
    const float* ffn_w2   = (const float*)d_in[17];
    const float* ffn_b2   = (const float*)d_in[18];
    const float* ln1_g    = (const float*)d_in[19];
    const float* ln1_b    = (const float*)d_in[20];
    const float* ln2_g    = (const float*)d_in[21];
    const float* ln2_b    = (const float*)d_in[22];
    float* out = (float*)d_out;

    float* f32 = nullptr;
    cudaGetSymbolAddress((void**)&f32, g_f32);

    static cudaStream_t s2 = nullptr;
    static cudaEvent_t evF = nullptr, evJ = nullptr;
    static bool init_done = false;
    if (!init_done) {
        cudaFuncSetAttribute(gemm_tf, cudaFuncAttributeMaxDynamicSharedMemorySize, 2 * GSTT);
        cudaFuncSetAttribute(mcov_tf, cudaFuncAttributeMaxDynamicSharedMemorySize, 2 * CSTT);
        cudaStreamCreateWithFlags(&s2, cudaStreamNonBlocking);
        cudaEventCreateWithFlags(&evF, cudaEventDisableTiming);
        cudaEventCreateWithFlags(&evJ, cudaEventDisableTiming);
        init_done = true;
    }

    float* qkv   = f32 + F_QKV;
    float* qkv2  = f32 + F_QKV2;
    float* att   = f32 + F_ATT;
    float* att2  = f32 + F_ATT2;
    float* bufb  = f32 + F_BUFB;
    float* bufh  = f32 + F_BUFH;
    float* bufc  = f32 + F_BUFC;
    float* se    = f32 + F_SE;
    float* sn    = f32 + F_SN;
    float* te    = f32 + F_TE;
    float* tn    = f32 + F_TN;
    float* bM    = f32 + F_M;
    float* bsim  = f32 + F_SIM;

    #define NP4 nullptr, nullptr, nullptr, nullptr

    // ---- fork ----
    cudaEventRecord(evF, 0);
    cudaStreamWaitEvent(s2, evF, 0);

    // ===== main stream: x-chain =====
    gemm_tf<<<dim3(3, 256), 256, 2 * GSTT>>>(
        x, nullptr, lw_in_w, lw_in_b, qkv, nullptr, NP4,
        nullptr, nullptr, nullptr, nullptr, 128, 384, EP_F32, 0, 0);
    lw_attn_k<<<dim3(256, 8), 64>>>(qkv, att);
    gemm_tf<<<dim3(1, 256), 256, 2 * GSTT>>>(
        att, nullptr, lw_out_w, lw_out_b, bufb, nullptr, NP4,
        x, nullptr, ln1_g, ln1_b, 128, 128, EP_LN, 0, 0);
    gemm_tf<<<dim3(4, 256), 256, 2 * GSTT>>>(
        bufb, nullptr, ffn_w1, ffn_b1, bufh, nullptr, NP4,
        nullptr, nullptr, nullptr, nullptr, 128, 512, EP_GELU, 0, 0);
    gemm_tf<<<dim3(1, 256), 256, 2 * GSTT>>>(
        bufh, nullptr, ffn_w2, ffn_b2, bufc, nullptr, NP4,
        bufb, nullptr, ln2_g, ln2_b, 512, 128, EP_LN2, 0, 0);

    // ===== stream 2: spatio-temporal chain =====
    zero_k<<<512, 256, 0, s2>>>(bM, 8 * 128 * 128);
    // dual launch: y<256 -> spatial (sp/spat_w -> sn,se); y>=256 -> temporal (tp/temp_w -> tn,te)
    gemm_tf<<<dim3(1, 512), 256, 2 * GSTT, s2>>>(
        sp, tp, spat_w, spat_b, sn, se,
        temp_w, temp_b, tn, te,
        nullptr, nullptr, nullptr, nullptr, 128, 128, EP_COS, 0, 256);
    mcov_tf<<<dim3(16, 8), 256, 2 * CSTT, s2>>>(sn, tn, bM);
    gemm_tf<<<dim3(1, 256), 256, 2 * GSTT, s2>>>(
        tn, nullptr, bM, nullptr, bsim, nullptr, NP4,
        sn, nullptr, nullptr, nullptr, 128, 0, EP_SIMDOT, 16384, 0);
    gemm_tf<<<dim3(3, 256), 256, 2 * GSTT, s2>>>(
        se, te, int_in_w, int_in_b, qkv2, nullptr, NP4,
        nullptr, nullptr, nullptr, nullptr, 128, 384, EP_F32, 0, 0);
    int_attn_k<<<SS, 64, 0, s2>>>(qkv2, att2);
    cudaEventRecord(evJ, s2);

    // ---- join + final ----
    cudaStreamWaitEvent(0, evJ, 0);
    gemm_tf<<<dim3(1, 256), 256, 2 * GSTT>>>(
        att2, nullptr, int_out_w, int_out_b, out, nullptr, NP4,
        bufc, bsim, nullptr, nullptr, 128, 128, EP_FINAL, 0, 0);
}